// round 14
// baseline (speedup 1.0000x reference)
#include <cuda_runtime.h>
#include <cuda_fp16.h>
#include <math.h>
#include <cstdint>

// ---------------- problem constants ----------------
#define Bb   2
#define Ss   2048
#define HID  2048
#define NHh  16
#define QLORA 1536
#define KVLORA 512
#define NOPE 128
#define ROPED 64
#define VDIM 128
#define QKD  192
#define ROWS (Bb*Ss)          // 4096
#define WKVA_NPAD 640
#define SCALEF 0.07216878364870322f
#define LN10K  9.210340371976184f

// ---------------- fp32 scratch ----------------
__device__ float g_qc   [(size_t)ROWS * QLORA];
__device__ float g_kvt  [(size_t)ROWS * (KVLORA+ROPED)];

// ---------------- fp16 activations ----------------
__device__ __half g_hs_h [(size_t)ROWS*HID];
__device__ __half g_qc_h [(size_t)ROWS*QLORA];
__device__ __half g_kvc_h[(size_t)ROWS*KVLORA];
__device__ __half g_at_h [(size_t)ROWS*NHh*VDIM];

// ---------------- fp16 transposed weights [N,K] ----------------
__device__ __half g_wqa_h [(size_t)QLORA*HID];
__device__ __half g_wqb_h [(size_t)(NHh*QKD)*QLORA];
__device__ __half g_wkva_h[(size_t)WKVA_NPAD*HID];
__device__ __half g_wkvb_h[(size_t)(NHh*(NOPE+VDIM))*KVLORA];
__device__ __half g_wo_h  [(size_t)HID*(NHh*VDIM)];

// ---------------- flash fp16 buffers, [b,h,s,d] ----------------
__device__ __half g_qfh[(size_t)ROWS*NHh*QKD];
__device__ __half g_kfh[(size_t)ROWS*NHh*QKD];
__device__ __half g_vfh[(size_t)ROWS*NHh*VDIM];

// ================= helpers =================
__device__ __forceinline__ uint32_t smem_u32(const void* p) {
    uint32_t a;
    asm("{ .reg .u64 t; cvta.to.shared.u64 t, %1; cvt.u32.u64 %0, t; }" : "=r"(a) : "l"(p));
    return a;
}

#define LDSM4(r, a) asm volatile( \
    "ldmatrix.sync.aligned.m8n8.x4.shared.b16 {%0,%1,%2,%3}, [%4];" \
    : "=r"((r)[0]),"=r"((r)[1]),"=r"((r)[2]),"=r"((r)[3]) : "r"(a))

#define LDSM4T(r, a) asm volatile( \
    "ldmatrix.sync.aligned.m8n8.x4.trans.shared.b16 {%0,%1,%2,%3}, [%4];" \
    : "=r"((r)[0]),"=r"((r)[1]),"=r"((r)[2]),"=r"((r)[3]) : "r"(a))

#define MMA16816(d, a, b0v, b1v) asm volatile( \
    "mma.sync.aligned.m16n8k16.row.col.f32.f16.f16.f32 " \
    "{%0,%1,%2,%3},{%4,%5,%6,%7},{%8,%9},{%0,%1,%2,%3};" \
    : "+f"((d)[0]),"+f"((d)[1]),"+f"((d)[2]),"+f"((d)[3]) \
    : "r"((a)[0]),"r"((a)[1]),"r"((a)[2]),"r"((a)[3]), "r"(b0v),"r"(b1v))

#define CP_ASYNC16(sa, ga) asm volatile( \
    "cp.async.cg.shared.global [%0], [%1], 16;" :: "r"(sa), "l"(ga))
#define CP_COMMIT() asm volatile("cp.async.commit_group;" ::: "memory")
#define CP_WAIT1()  asm volatile("cp.async.wait_group 1;" ::: "memory")
#define CP_WAIT0()  asm volatile("cp.async.wait_group 0;" ::: "memory")

#define GRID_SYNC() cudaGridDependencySynchronize()

// ================= fp16 HMMA GEMM mainloop, BK=64 =================
#define BK 64
#define PITCHH 72
#define TILE_B (128*PITCHH*2)          // 18432
#define STAGE_B (2*TILE_B)             // 36864
#define NSTAGE 3
#define GEMM_SMEM (NSTAGE*STAGE_B)     // 110592

__device__ __forceinline__ void gemm_mainloop(
    const __half* __restrict__ gA, const __half* __restrict__ gB, int K,
    uint32_t sbase, float acc[2][8][4],
    int tid, int lane, int warpM, int warpN) {

    auto issue_loads = [&](int c, int s) {
        int k0 = c * BK;
        uint32_t st = sbase + s * STAGE_B;
#pragma unroll
        for (int j = 0; j < 4; j++) {
            int seg = tid + j * 256;
            int r = seg >> 3, cc = seg & 7;
            CP_ASYNC16(st + r * (PITCHH * 2) + cc * 16, gA + (size_t)r * K + k0 + cc * 8);
            CP_ASYNC16(st + TILE_B + r * (PITCHH * 2) + cc * 16, gB + (size_t)r * K + k0 + cc * 8);
        }
        CP_COMMIT();
    };

#pragma unroll
    for (int i = 0; i < 2; i++)
#pragma unroll
        for (int j = 0; j < 8; j++)
#pragma unroll
            for (int k = 0; k < 4; k++) acc[i][j][k] = 0.f;

    int a_r = warpM * 32 + (lane & 15);
    int a_c8 = (lane >> 4) << 3;
    int b_r = warpN * 64 + ((lane >> 4) << 3) + (lane & 7);
    int b_c8 = ((lane >> 3) & 1) << 3;

    auto compute = [&](int s) {
        uint32_t st = sbase + s * STAGE_B;
#pragma unroll
        for (int ki = 0; ki < 4; ki++) {
            uint32_t ah[2][4];
#pragma unroll
            for (int mi = 0; mi < 2; mi++) {
                uint32_t off = (uint32_t)((a_r + mi * 16) * (PITCHH * 2) + (ki * 16 + a_c8) * 2);
                LDSM4(ah[mi], st + off);
            }
            uint32_t bh[4][4];
#pragma unroll
            for (int nb = 0; nb < 4; nb++) {
                uint32_t off = (uint32_t)((b_r + nb * 16) * (PITCHH * 2) + (ki * 16 + b_c8) * 2);
                LDSM4(bh[nb], st + TILE_B + off);
            }
#pragma unroll
            for (int mi = 0; mi < 2; mi++)
#pragma unroll
                for (int nb = 0; nb < 4; nb++) {
                    MMA16816(acc[mi][2*nb],   ah[mi], bh[nb][0], bh[nb][1]);
                    MMA16816(acc[mi][2*nb+1], ah[mi], bh[nb][2], bh[nb][3]);
                }
        }
    };

    int nc = K / BK;
    issue_loads(0, 0);
    issue_loads(1, 1);
    for (int c = 0; c < nc; c++) {
        int s = c % NSTAGE;
        if (c + 1 < nc) { CP_WAIT1(); } else { CP_WAIT0(); }
        __syncthreads();
        if (c + 2 < nc) issue_loads(c + 2, (c + 2) % NSTAGE);
        compute(s);
    }
}

// ================= merged G1+G3 =================
__global__ void __launch_bounds__(256, 2) gemm_a(
    const __half* __restrict__ hs, const __half* __restrict__ wqa,
    const __half* __restrict__ wkva,
    float* __restrict__ qc, float* __restrict__ kvt) {
    GRID_SYNC();
    extern __shared__ char sm[];
    uint32_t sbase = smem_u32(sm);
    int tid = threadIdx.x, lane = tid & 31, wid = tid >> 5;
    int warpM = wid & 3, warpN = wid >> 2;
    int row0 = blockIdx.y * 128;
    int bx = blockIdx.x;

    const __half* B;
    float* C; int cN, col0, Nlim;
    if (bx < 12) { col0 = bx * 128;        B = wqa  + (size_t)col0 * HID; C = qc;  cN = QLORA; Nlim = QLORA; }
    else         { col0 = (bx - 12) * 128; B = wkva + (size_t)col0 * HID; C = kvt; cN = KVLORA+ROPED; Nlim = KVLORA+ROPED; }

    float acc[2][8][4];
    gemm_mainloop(hs + (size_t)row0 * HID, B, HID, sbase, acc, tid, lane, warpM, warpN);

    int g = lane >> 2, t = lane & 3;
#pragma unroll
    for (int mi = 0; mi < 2; mi++)
#pragma unroll
        for (int n8 = 0; n8 < 8; n8++) {
            int col = col0 + warpN * 64 + n8 * 8 + t * 2;
            if (col < Nlim) {
                int r0 = row0 + warpM * 32 + mi * 16 + g;
                float* p0 = C + (size_t)r0 * cN + col;
                p0[0] = acc[mi][n8][0]; p0[1] = acc[mi][n8][1];
                float* p1 = p0 + (size_t)8 * cN;
                p1[0] = acc[mi][n8][2]; p1[1] = acc[mi][n8][3];
            }
        }
}

// ================= merged G2+G4 =================
__global__ void __launch_bounds__(256, 2) gemm_b(
    const __half* __restrict__ qch, const __half* __restrict__ wqb,
    const __half* __restrict__ kvch, const __half* __restrict__ wkvb,
    const int* __restrict__ pos,
    __half* __restrict__ qfh, __half* __restrict__ kfh, __half* __restrict__ vfh) {
    GRID_SYNC();
    extern __shared__ char sm[];
    uint32_t sbase = smem_u32(sm);
    int tid = threadIdx.x, lane = tid & 31, wid = tid >> 5;
    int warpM = wid & 3, warpN = wid >> 2;
    int row0 = blockIdx.y * 128;
    int bx = blockIdx.x;
    int g = lane >> 2, t4 = lane & 3;

    if (bx < 24) {
        int col0 = bx * 128;
        float acc[2][8][4];
        gemm_mainloop(qch + (size_t)row0 * QLORA, wqb + (size_t)col0 * QLORA, QLORA,
                      sbase, acc, tid, lane, warpM, warpN);

        int colw = col0 + warpN * 64;
        int hH = colw / 192;
        int dbase = colw % 192;
        if (dbase != 128) {
#pragma unroll
            for (int mi = 0; mi < 2; mi++)
#pragma unroll
                for (int rr = 0; rr < 2; rr++) {
                    int row = row0 + warpM * 32 + mi * 16 + g + rr * 8;
                    int b = row >> 11, srow = row & 2047;
                    size_t obase = ((size_t)(b * NHh + hH) * Ss + srow) * QKD;
#pragma unroll
                    for (int n8 = 0; n8 < 8; n8++) {
                        int d = dbase + n8 * 8 + t4 * 2;
                        *(__half2*)(qfh + obase + d) = __floats2half2_rn(
                            acc[mi][n8][rr*2] * SCALEF, acc[mi][n8][rr*2+1] * SCALEF);
                    }
                }
        } else {
#pragma unroll
            for (int mi = 0; mi < 2; mi++)
#pragma unroll
                for (int rr = 0; rr < 2; rr++) {
                    int row = row0 + warpM * 32 + mi * 16 + g + rr * 8;
                    int b = row >> 11, srow = row & 2047;
                    float p = (float)pos[b * Ss + srow];
                    size_t obase = ((size_t)(b * NHh + hH) * Ss + srow) * QKD;
#pragma unroll
                    for (int n8 = 0; n8 < 4; n8++) {
                        int j0 = n8 * 8 + t4 * 2;
                        float if0 = __expf(-(float)j0 * (LN10K / 32.f));
                        float if1 = __expf(-(float)(j0 + 1) * (LN10K / 32.f));
                        float s0, c0, s1, c1;
                        __sincosf(p * if0, &s0, &c0);
                        __sincosf(p * if1, &s1, &c1);
                        float x1a = acc[mi][n8][rr*2],   x2a = acc[mi][n8+4][rr*2];
                        float x1b = acc[mi][n8][rr*2+1], x2b = acc[mi][n8+4][rr*2+1];
                        *(__half2*)(qfh + obase + 128 + j0) = __floats2half2_rn(
                            (x1a * c0 - x2a * s0) * SCALEF, (x1b * c1 - x2b * s1) * SCALEF);
                        *(__half2*)(qfh + obase + 160 + j0) = __floats2half2_rn(
                            (x2a * c0 + x1a * s0) * SCALEF, (x2b * c1 + x1b * s1) * SCALEF);
                    }
                }
        }
    } else {
        int col0 = (bx - 24) * 128;
        float acc[2][8][4];
        gemm_mainloop(kvch + (size_t)row0 * KVLORA, wkvb + (size_t)col0 * KVLORA, KVLORA,
                      sbase, acc, tid, lane, warpM, warpN);

        int hH = col0 >> 8;
        int isV = (col0 >> 7) & 1;
        __half* D = isV ? vfh : kfh;
        int stride = isV ? VDIM : QKD;
#pragma unroll
        for (int mi = 0; mi < 2; mi++)
#pragma unroll
            for (int n8 = 0; n8 < 8; n8++) {
                int col = col0 + warpN * 64 + n8 * 8 + t4 * 2;
                int d = col & 127;
#pragma unroll
                for (int rr = 0; rr < 2; rr++) {
                    int r0 = row0 + warpM * 32 + mi * 16 + g + rr * 8;
                    int b = r0 >> 11, srow = r0 & 2047;
                    size_t o = ((size_t)(b * NHh + hH) * Ss + srow) * stride + d;
                    *(__half2*)(D + o) = __floats2half2_rn(acc[mi][n8][rr*2], acc[mi][n8][rr*2+1]);
                }
            }
    }
}

// ================= G5 =================
__global__ void __launch_bounds__(256, 2) gemm_c(
    const __half* __restrict__ at, const __half* __restrict__ wo,
    float* __restrict__ out) {
    GRID_SYNC();
    extern __shared__ char sm[];
    uint32_t sbase = smem_u32(sm);
    int tid = threadIdx.x, lane = tid & 31, wid = tid >> 5;
    int warpM = wid & 3, warpN = wid >> 2;
    int row0 = blockIdx.y * 128, col0 = blockIdx.x * 128;

    float acc[2][8][4];
    gemm_mainloop(at + (size_t)row0 * HID, wo + (size_t)col0 * HID, HID,
                  sbase, acc, tid, lane, warpM, warpN);

    int g = lane >> 2, t = lane & 3;
#pragma unroll
    for (int mi = 0; mi < 2; mi++)
#pragma unroll
        for (int n8 = 0; n8 < 8; n8++) {
            int col = col0 + warpN * 64 + n8 * 8 + t * 2;
            int r0 = row0 + warpM * 32 + mi * 16 + g;
            float* p0 = out + (size_t)r0 * HID + col;
            p0[0] = acc[mi][n8][0]; p0[1] = acc[mi][n8][1];
            float* p1 = p0 + (size_t)8 * HID;
            p1[0] = acc[mi][n8][2]; p1[1] = acc[mi][n8][3];
        }
}

// ================= merged prep kernels =================
__device__ __forceinline__ void do_transpose(
    const float* __restrict__ W, __half* __restrict__ Th,
    int K, int srcN, int colTiles, int tile, int tid) {
    __shared__ float t[32][33];
    int n0 = (tile % colTiles) * 32, k0 = (tile / colTiles) * 32;
    int tx = tid & 31, ty = tid >> 5;
#pragma unroll
    for (int i = 0; i < 4; i++) {
        int k = k0 + ty + i * 8, n = n0 + tx;
        t[ty + i * 8][tx] = (n < srcN) ? W[(size_t)k * srcN + n] : 0.f;
    }
    __syncthreads();
#pragma unroll
    for (int i = 0; i < 4; i++) {
        int n = n0 + ty + i * 8;
        Th[(size_t)n * K + k0 + tx] = __float2half(t[tx][ty + i * 8]);
    }
}

__global__ void prep_main(const float* __restrict__ hs, __half* __restrict__ hsh,
                          const float* __restrict__ wqa, __half* __restrict__ wqah,
                          const float* __restrict__ wkva, __half* __restrict__ wkvah) {
    int bx = blockIdx.x, tid = threadIdx.x;
    if (bx < 4096) {
        size_t i = ((size_t)bx * 256 + tid) * 8;
        float4 v0 = *(const float4*)(hs + i);
        float4 v1 = *(const float4*)(hs + i + 4);
        *(__half2*)(hsh + i)     = __floats2half2_rn(v0.x, v0.y);
        *(__half2*)(hsh + i + 2) = __floats2half2_rn(v0.z, v0.w);
        *(__half2*)(hsh + i + 4) = __floats2half2_rn(v1.x, v1.y);
        *(__half2*)(hsh + i + 6) = __floats2half2_rn(v1.z, v1.w);
    } else if (bx < 4096 + 3072) {
        do_transpose(wqa, wqah, HID, QLORA, QLORA/32, bx - 4096, tid);
    } else {
        do_transpose(wkva, wkvah, HID, KVLORA+ROPED, WKVA_NPAD/32, bx - 7168, tid);
    }
}

__global__ void prep_aux(const float* __restrict__ wqb, __half* __restrict__ wqbh,
                         const float* __restrict__ wkvb, __half* __restrict__ wkvbh,
                         const float* __restrict__ wo, __half* __restrict__ woh) {
    int bx = blockIdx.x, tid = threadIdx.x;
    if (bx < 4608) {
        do_transpose(wqb, wqbh, QLORA, NHh*QKD, (NHh*QKD)/32, bx, tid);
    } else if (bx < 4608 + 2048) {
        do_transpose(wkvb, wkvbh, KVLORA, NHh*(NOPE+VDIM), (NHh*(NOPE+VDIM))/32, bx - 4608, tid);
    } else {
        do_transpose(wo, woh, NHh*VDIM, HID, HID/32, bx - 6656, tid);
    }
}

// ================= register-resident single-pass norm =================
__device__ __forceinline__ float block_reduce_sum(float v, float* red8, int tid) {
#pragma unroll
    for (int off = 16; off > 0; off >>= 1)
        v += __shfl_xor_sync(0xffffffffu, v, off);
    if ((tid & 31) == 0) red8[tid >> 5] = v;
    __syncthreads();
    float s = (tid < 8) ? red8[tid] : 0.f;
#pragma unroll
    for (int off = 4; off > 0; off >>= 1)
        s += __shfl_xor_sync(0xffffffffu, s, off);
    if (tid == 0) red8[0] = s;
    __syncthreads();
    return red8[0];
}

__global__ void norm_fused(const float* __restrict__ qc, const float* __restrict__ qw,
                           const float* __restrict__ kvt, const float* __restrict__ kvw,
                           const int* __restrict__ pos,
                           __half* __restrict__ qch, __half* __restrict__ kvch,
                           __half* __restrict__ kfh) {
    GRID_SYNC();
    __shared__ float red8[8];
    __shared__ float rop[64];
    int tid = threadIdx.x;
    if (blockIdx.x < ROWS) {
        int row = blockIdx.x;
        const float* r = qc + (size_t)row * QLORA;
        float4 v4 = *(const float4*)(r + 4 * tid);
        float2 v2 = *(const float2*)(r + 1024 + 2 * tid);
        float ss = v4.x*v4.x + v4.y*v4.y + v4.z*v4.z + v4.w*v4.w + v2.x*v2.x + v2.y*v2.y;
        float tot = block_reduce_sum(ss, red8, tid);
        float scale = rsqrtf(tot / (float)QLORA + 1e-6f);
        float4 w4 = *(const float4*)(qw + 4 * tid);
        float2 w2 = *(const float2*)(qw + 1024 + 2 * tid);
        __half* o = qch + (size_t)row * QLORA;
        *(__half2*)(o + 4*tid)        = __floats2half2_rn(v4.x*scale*w4.x, v4.y*scale*w4.y);
        *(__half2*)(o + 4*tid + 2)    = __floats2half2_rn(v4.z*scale*w4.z, v4.w*scale*w4.w);
        *(__half2*)(o + 1024 + 2*tid) = __floats2half2_rn(v2.x*scale*w2.x, v2.y*scale*w2.y);
    } else {
        int row = blockIdx.x - ROWS;
        const float* r = kvt + (size_t)row * (KVLORA + ROPED);
        float2 v2 = *(const float2*)(r + 2 * tid);
        float ss = v2.x*v2.x + v2.y*v2.y;
        if (tid < 32) {
            float p = (float)pos[row];
            float inv_freq = __expf(-(float)tid * (LN10K / 32.f));
            float c, s;
            __sincosf(p * inv_freq, &s, &c);
            float x1 = r[KVLORA + tid];
            float x2 = r[KVLORA + 32 + tid];
            rop[tid]      = x1 * c - x2 * s;
            rop[tid + 32] = x2 * c + x1 * s;
        }
        float tot = block_reduce_sum(ss, red8, tid);
        float scale = rsqrtf(tot / (float)KVLORA + 1e-6f);
        float2 w2 = *(const float2*)(kvw + 2 * tid);
        *(__half2*)(kvch + (size_t)row * KVLORA + 2*tid) =
            __floats2half2_rn(v2.x*scale*w2.x, v2.y*scale*w2.y);
        int b = row >> 11, srow = row & 2047;
        for (int e = tid; e < NHh * ROPED; e += 256) {
            int h = e >> 6, d = e & 63;
            size_t o = ((size_t)(b * NHh + h) * Ss + srow) * QKD + NOPE + d;
            kfh[o] = __float2half(rop[d]);
        }
    }
}

// ================= fp16 flash v4: kv-tile 128, Q in registers ===============
#define FQ_PITCH 400
#define FV_PITCH 272
#define FQ_SZ    (128*FQ_PITCH)           // 51200
#define FK_SZ    (128*FQ_PITCH)           // 51200
#define FV_SZ    (128*FV_PITCH)           // 34816
#define F_OFF_K  FQ_SZ
#define F_OFF_V  (F_OFF_K + 2*FK_SZ)      // 153600
#define FLASH_SMEM (F_OFF_V + 2*FV_SZ)    // 223232

__global__ void __launch_bounds__(256, 1) flash_mma(
    const __half* __restrict__ qh, const __half* __restrict__ kh,
    const __half* __restrict__ vh, __half* __restrict__ oh) {
    GRID_SYNC();
    extern __shared__ char sm[];
    uint32_t sb = smem_u32(sm);

    int qt = (gridDim.x - 1) - blockIdx.x;   // heavy CTAs first
    int h = blockIdx.y, b = blockIdx.z;
    int q0 = qt * 128;
    int tid = threadIdx.x, lane = tid & 31, w = tid >> 5;
    int bh = b * NHh + h;

    const __half* qhb = qh + ((size_t)bh * Ss + q0) * QKD;
    const __half* khb = kh + (size_t)bh * Ss * QKD;
    const __half* vhb = vh + (size_t)bh * Ss * VDIM;

    // ---- load Q tile (group 0) ----
#pragma unroll
    for (int i = 0; i < 12; i++) {
        int e = tid + i * 256;
        int r = e / 24, c = e % 24;
        CP_ASYNC16(sb + r * FQ_PITCH + c * 16, qhb + (size_t)r * QKD + c * 8);
    }
    CP_COMMIT();

    auto load_kv = [&](int kt, int s) {
        int k0 = kt * 128;
        uint32_t kst = sb + F_OFF_K + s * FK_SZ;
        uint32_t vst = sb + F_OFF_V + s * FV_SZ;
#pragma unroll
        for (int i = 0; i < 12; i++) {
            int e = tid + i * 256;           // 3072 chunks
            int r = e / 24, c = e % 24;
            CP_ASYNC16(kst + r * FQ_PITCH + c * 16, khb + (size_t)(k0 + r) * QKD + c * 8);
        }
#pragma unroll
        for (int i = 0; i < 8; i++) {
            int e = tid + i * 256;           // 2048 chunks
            int r = e >> 4, c = e & 15;
            CP_ASYNC16(vst + r * FV_PITCH + c * 16, vhb + (size_t)(k0 + r) * VDIM + c * 8);
        }
        CP_COMMIT();
    };

    load_kv(0, 0);                           // group 1

    int a_r = w * 16 + (lane & 15);
    int a_c8 = (lane >> 4) << 3;
    int b_r = ((lane >> 4) << 3) + (lane & 7);
    int b_c8 = ((lane >> 3) & 1) << 3;
    int vt_r = lane & 15;
    int vt_c8 = (lane >> 4) << 3;

    int g = lane >> 2, t4 = lane & 3;

    // ---- wait for Q, hoist Q fragments into registers ----
    CP_WAIT1();
    __syncthreads();
    uint32_t qfr[12][4];
#pragma unroll
    for (int kk = 0; kk < 12; kk++)
        LDSM4(qfr[kk], sb + (uint32_t)(a_r * FQ_PITCH + (kk * 16 + a_c8) * 2));

    float m0 = -INFINITY, m1 = -INFINITY, l0 = 0.f, l1 = 0.f;
    float O[16][4];
#pragma unroll
    for (int j = 0; j < 16; j++)
#pragma unroll
        for (int k = 0; k < 4; k++) O[j][k] = 0.f;

    int qrow0 = q0 + w * 16 + g;
    int qrow1 = qrow0 + 8;

    int nkt = qt + 1;                        // kv tiles of 128

    for (int kt = 0; kt < nkt; kt++) {
        int s = kt & 1;
        if (kt + 1 < nkt) { load_kv(kt + 1, s ^ 1); CP_WAIT1(); }
        else              { CP_WAIT0(); }
        __syncthreads();

        uint32_t kst = sb + F_OFF_K + s * FK_SZ;
        uint32_t vst = sb + F_OFF_V + s * FV_SZ;
        int k0 = kt * 128;

        // ---- QK^T: warp computes 16x128 scores ----
        float sc[16][4];
#pragma unroll
        for (int j = 0; j < 16; j++)
#pragma unroll
            for (int k = 0; k < 4; k++) sc[j][k] = 0.f;

#pragma unroll
        for (int kk = 0; kk < 12; kk++) {
#pragma unroll
            for (int nb = 0; nb < 8; nb++) {
                uint32_t bhf[4];
                LDSM4(bhf, kst + (uint32_t)((nb * 16 + b_r) * FQ_PITCH + (kk * 16 + b_c8) * 2));
                MMA16816(sc[2*nb],   qfr[kk], bhf[0], bhf[1]);
                MMA16816(sc[2*nb+1], qfr[kk], bhf[2], bhf[3]);
            }
        }

        // ---- causal mask (diagonal tile only) ----
        if (kt == qt) {
#pragma unroll
            for (int j = 0; j < 16; j++) {
                int col = k0 + j * 8 + t4 * 2;
                if (col     > qrow0) sc[j][0] = -INFINITY;
                if (col + 1 > qrow0) sc[j][1] = -INFINITY;
                if (col     > qrow1) sc[j][2] = -INFINITY;
                if (col + 1 > qrow1) sc[j][3] = -INFINITY;
            }
        }

        // ---- online softmax ----
        float rm0 = -INFINITY, rm1 = -INFINITY;
#pragma unroll
        for (int j = 0; j < 16; j++) {
            rm0 = fmaxf(rm0, fmaxf(sc[j][0], sc[j][1]));
            rm1 = fmaxf(rm1, fmaxf(sc[j][2], sc[j][3]));
        }
        rm0 = fmaxf(rm0, __shfl_xor_sync(0xffffffffu, rm0, 1));
        rm0 = fmaxf(rm0, __shfl_xor_sync(0xffffffffu, rm0, 2));
        rm1 = fmaxf(rm1, __shfl_xor_sync(0xffffffffu, rm1, 1));
        rm1 = fmaxf(rm1, __shfl_xor_sync(0xffffffffu, rm1, 2));
        float nm0 = fmaxf(m0, rm0), nm1 = fmaxf(m1, rm1);
        float rs0 = 0.f, rs1 = 0.f;
#pragma unroll
        for (int j = 0; j < 16; j++) {
            sc[j][0] = __expf(sc[j][0] - nm0);
            sc[j][1] = __expf(sc[j][1] - nm0);
            sc[j][2] = __expf(sc[j][2] - nm1);
            sc[j][3] = __expf(sc[j][3] - nm1);
            rs0 += sc[j][0] + sc[j][1];
            rs1 += sc[j][2] + sc[j][3];
        }
        rs0 += __shfl_xor_sync(0xffffffffu, rs0, 1);
        rs0 += __shfl_xor_sync(0xffffffffu, rs0, 2);
        rs1 += __shfl_xor_sync(0xffffffffu, rs1, 1);
        rs1 += __shfl_xor_sync(0xffffffffu, rs1, 2);
        float al0 = __expf(m0 - nm0), al1 = __expf(m1 - nm1);
        l0 = l0 * al0 + rs0; l1 = l1 * al1 + rs1;
        m0 = nm0; m1 = nm1;
#pragma unroll
        for (int j = 0; j < 16; j++) {
            O[j][0] *= al0; O[j][1] *= al0;
            O[j][2] *= al1; O[j][3] *= al1;
        }

        // ---- P@V in two 64-key halves (bounds register pressure) ----
#pragma unroll
        for (int half = 0; half < 2; half++) {
            uint32_t ph2[8][2];
#pragma unroll
            for (int j = 0; j < 8; j++) {
                int js = half * 8 + j;
                __half2 p01 = __floats2half2_rn(sc[js][0], sc[js][1]);
                __half2 p23 = __floats2half2_rn(sc[js][2], sc[js][3]);
                ph2[j][0] = *(uint32_t*)&p01;
                ph2[j][1] = *(uint32_t*)&p23;
            }
#pragma unroll
            for (int kk = 0; kk < 4; kk++) {
                uint32_t ah[4] = { ph2[2*kk][0], ph2[2*kk][1], ph2[2*kk+1][0], ph2[2*kk+1][1] };
                int kr = half * 64 + kk * 16;
#pragma unroll
                for (int j2 = 0; j2 < 8; j2++) {
                    uint32_t vhf[4];
                    LDSM4T(vhf, vst + (uint32_t)((kr + vt_r) * FV_PITCH + (j2 * 16 + vt_c8) * 2));
                    MMA16816(O[2*j2],   ah, vhf[0], vhf[1]);
                    MMA16816(O[2*j2+1], ah, vhf[2], vhf[3]);
                }
            }
        }
        __syncthreads();
    }

    // ---- epilogue ----
    float inv0 = 1.f / l0, inv1 = 1.f / l1;
    size_t ob0 = ((size_t)(b * Ss + qrow0)) * (NHh * VDIM) + h * VDIM;
    size_t ob1 = ((size_t)(b * Ss + qrow1)) * (NHh * VDIM) + h * VDIM;
#pragma unroll
    for (int j = 0; j < 16; j++) {
        int d = j * 8 + t4 * 2;
        *(__half2*)(oh + ob0 + d) = __floats2half2_rn(O[j][0] * inv0, O[j][1] * inv0);
        *(__half2*)(oh + ob1 + d) = __floats2half2_rn(O[j][2] * inv1, O[j][3] * inv1);
    }
}

// ================= launch =================
extern "C" void kernel_launch(void* const* d_in, const int* in_sizes, int n_in,
                              void* d_out, int out_size) {
    const float* hs     = (const float*)d_in[0];
    const int*   pos    = (const int*)  d_in[1];
    const float* w_q_a  = (const float*)d_in[3];
    const float* q_ln   = (const float*)d_in[4];
    const float* w_q_b  = (const float*)d_in[5];
    const float* w_kv_a = (const float*)d_in[6];
    const float* kv_ln  = (const float*)d_in[7];
    const float* w_kv_b = (const float*)d_in[8];
    const float* w_o    = (const float*)d_in[9];
    float* out = (float*)d_out;

    float *qc, *kvt;
    cudaGetSymbolAddress((void**)&qc,  g_qc);
    cudaGetSymbolAddress((void**)&kvt, g_kvt);

    __half *hs_h,*qc_h,*kvc_h,*at_h;
    __half *wqa_h,*wqb_h,*wkva_h,*wkvb_h,*wo_h;
    __half *qfh,*kfh,*vfh;
    cudaGetSymbolAddress((void**)&hs_h,  g_hs_h);
    cudaGetSymbolAddress((void**)&qc_h,  g_qc_h);
    cudaGetSymbolAddress((void**)&kvc_h, g_kvc_h);
    cudaGetSymbolAddress((void**)&at_h,  g_at_h);
    cudaGetSymbolAddress((void**)&wqa_h, g_wqa_h);
    cudaGetSymbolAddress((void**)&wqb_h, g_wqb_h);
    cudaGetSymbolAddress((void**)&wkva_h,g_wkva_h);
    cudaGetSymbolAddress((void**)&wkvb_h,g_wkvb_h);
    cudaGetSymbolAddress((void**)&wo_h,  g_wo_h);
    cudaGetSymbolAddress((void**)&qfh,   g_qfh);
    cudaGetSymbolAddress((void**)&kfh,   g_kfh);
    cudaGetSymbolAddress((void**)&vfh,   g_vfh);

    cudaFuncSetAttribute(gemm_a, cudaFuncAttributeMaxDynamicSharedMemorySize, GEMM_SMEM);
    cudaFuncSetAttribute(gemm_b, cudaFuncAttributeMaxDynamicSharedMemorySize, GEMM_SMEM);
    cudaFuncSetAttribute(gemm_c, cudaFuncAttributeMaxDynamicSharedMemorySize, GEMM_SMEM);
    cudaFuncSetAttribute(flash_mma, cudaFuncAttributeMaxDynamicSharedMemorySize, FLASH_SMEM);

    cudaStream_t s2;
    cudaStreamCreateWithFlags(&s2, cudaStreamNonBlocking);
    cudaEvent_t evFork, evJoin;
    cudaEventCreateWithFlags(&evFork, cudaEventDisableTiming);
    cudaEventCreateWithFlags(&evJoin, cudaEventDisableTiming);

    cudaEventRecord(evFork, 0);
    cudaStreamWaitEvent(s2, evFork, 0);
    prep_aux<<<4608 + 2048 + 4096, 256, 0, s2>>>(w_q_b, wqb_h, w_kv_b, wkvb_h, w_o, wo_h);
    cudaEventRecord(evJoin, s2);

    prep_main<<<4096 + 3072 + 1280, 256>>>(hs, hs_h, w_q_a, wqa_h, w_kv_a, wkva_h);

    // PDL launch helper: programmatic serialization on stream 0
    cudaLaunchAttribute pdlAttr[1];
    pdlAttr[0].id = cudaLaunchAttributeProgrammaticStreamSerialization;
    pdlAttr[0].val.programmaticStreamSerializationAllowed = 1;

    {
        cudaLaunchConfig_t cfg{};
        cfg.gridDim = dim3(12 + WKVA_NPAD/128, ROWS/128);
        cfg.blockDim = dim3(256);
        cfg.dynamicSmemBytes = GEMM_SMEM;
        cfg.stream = 0; cfg.attrs = pdlAttr; cfg.numAttrs = 1;
        cudaLaunchKernelEx(&cfg, gemm_a, hs_h, wqa_h, wkva_h, qc, kvt);
    }
    {
        cudaLaunchConfig_t cfg{};
        cfg.gridDim = dim3(2*ROWS);
        cfg.blockDim = dim3(256);
        cfg.dynamicSmemBytes = 0;
        cfg.stream = 0; cfg.attrs = pdlAttr; cfg.numAttrs = 1;
        cudaLaunchKernelEx(&cfg, norm_fused, (const float*)qc, q_ln, (const float*)kvt, kv_ln,
                           pos, qc_h, kvc_h, kfh);
    }

    cudaStreamWaitEvent(0, evJoin, 0);

    {
        cudaLaunchConfig_t cfg{};
        cfg.gridDim = dim3(24 + 32, ROWS/128);
        cfg.blockDim = dim3(256);
        cfg.dynamicSmemBytes = GEMM_SMEM;
        cfg.stream = 0; cfg.attrs = pdlAttr; cfg.numAttrs = 1;
        cudaLaunchKernelEx(&cfg, gemm_b, (const __half*)qc_h, (const __half*)wqb_h,
                           (const __half*)kvc_h, (const __half*)wkvb_h, pos, qfh, kfh, vfh);
    }
    {
        cudaLaunchConfig_t cfg{};
        cfg.gridDim = dim3(Ss/128, NHh, Bb);
        cfg.blockDim = dim3(256);
        cfg.dynamicSmemBytes = FLASH_SMEM;
        cfg.stream = 0; cfg.attrs = pdlAttr; cfg.numAttrs = 1;
        cudaLaunchKernelEx(&cfg, flash_mma, (const __half*)qfh, (const __half*)kfh,
                           (const __half*)vfh, at_h);
    }
    {
        cudaLaunchConfig_t cfg{};
        cfg.gridDim = dim3(HID/128, ROWS/128);
        cfg.blockDim = dim3(256);
        cfg.dynamicSmemBytes = GEMM_SMEM;
        cfg.stream = 0; cfg.attrs = pdlAttr; cfg.numAttrs = 1;
        cudaLaunchKernelEx(&cfg, gemm_c, (const __half*)at_h, (const __half*)wo_h, out);
    }

    cudaEventDestroy(evFork);
    cudaEventDestroy(evJoin);
    cudaStreamDestroy(s2);
}

// round 15
// speedup vs baseline: 1.0124x; 1.0124x over previous
#include <cuda_runtime.h>
#include <cuda_fp16.h>
#include <math.h>
#include <cstdint>

// ---------------- problem constants ----------------
#define Bb   2
#define Ss   2048
#define HID  2048
#define NHh  16
#define QLORA 1536
#define KVLORA 512
#define NOPE 128
#define ROPED 64
#define VDIM 128
#define QKD  192
#define ROWS (Bb*Ss)          // 4096
#define WKVA_NPAD 640
#define SCALEF 0.07216878364870322f
#define LN10K  9.210340371976184f

// ---------------- fp32 scratch ----------------
__device__ float g_qc   [(size_t)ROWS * QLORA];
__device__ float g_kvt  [(size_t)ROWS * (KVLORA+ROPED)];

// ---------------- fp16 activations ----------------
__device__ __half g_hs_h [(size_t)ROWS*HID];
__device__ __half g_qc_h [(size_t)ROWS*QLORA];
__device__ __half g_kvc_h[(size_t)ROWS*KVLORA];
__device__ __half g_at_h [(size_t)ROWS*NHh*VDIM];

// ---------------- fp16 transposed weights [N,K] ----------------
__device__ __half g_wqa_h [(size_t)QLORA*HID];
__device__ __half g_wqb_h [(size_t)(NHh*QKD)*QLORA];
__device__ __half g_wkva_h[(size_t)WKVA_NPAD*HID];
__device__ __half g_wkvb_h[(size_t)(NHh*(NOPE+VDIM))*KVLORA];
__device__ __half g_wo_h  [(size_t)HID*(NHh*VDIM)];

// ---------------- flash fp16 buffers, [b,h,s,d] ----------------
__device__ __half g_qfh[(size_t)ROWS*NHh*QKD];
__device__ __half g_kfh[(size_t)ROWS*NHh*QKD];
__device__ __half g_vfh[(size_t)ROWS*NHh*VDIM];

// ================= helpers =================
__device__ __forceinline__ uint32_t smem_u32(const void* p) {
    uint32_t a;
    asm("{ .reg .u64 t; cvta.to.shared.u64 t, %1; cvt.u32.u64 %0, t; }" : "=r"(a) : "l"(p));
    return a;
}

#define LDSM4(r, a) asm volatile( \
    "ldmatrix.sync.aligned.m8n8.x4.shared.b16 {%0,%1,%2,%3}, [%4];" \
    : "=r"((r)[0]),"=r"((r)[1]),"=r"((r)[2]),"=r"((r)[3]) : "r"(a))

#define LDSM4T(r, a) asm volatile( \
    "ldmatrix.sync.aligned.m8n8.x4.trans.shared.b16 {%0,%1,%2,%3}, [%4];" \
    : "=r"((r)[0]),"=r"((r)[1]),"=r"((r)[2]),"=r"((r)[3]) : "r"(a))

#define MMA16816(d, a, b0v, b1v) asm volatile( \
    "mma.sync.aligned.m16n8k16.row.col.f32.f16.f16.f32 " \
    "{%0,%1,%2,%3},{%4,%5,%6,%7},{%8,%9},{%0,%1,%2,%3};" \
    : "+f"((d)[0]),"+f"((d)[1]),"+f"((d)[2]),"+f"((d)[3]) \
    : "r"((a)[0]),"r"((a)[1]),"r"((a)[2]),"r"((a)[3]), "r"(b0v),"r"(b1v))

#define CP_ASYNC16(sa, ga) asm volatile( \
    "cp.async.cg.shared.global [%0], [%1], 16;" :: "r"(sa), "l"(ga))
#define CP_COMMIT() asm volatile("cp.async.commit_group;" ::: "memory")
#define CP_WAIT1()  asm volatile("cp.async.wait_group 1;" ::: "memory")
#define CP_WAIT0()  asm volatile("cp.async.wait_group 0;" ::: "memory")

#define GRID_SYNC() cudaGridDependencySynchronize()

// ================= fp16 HMMA GEMM mainloop, BK=64 =================
#define BK 64
#define PITCHH 72
#define TILE_B (128*PITCHH*2)          // 18432
#define STAGE_B (2*TILE_B)             // 36864
#define NSTAGE 3
#define GEMM_SMEM (NSTAGE*STAGE_B)     // 110592

__device__ __forceinline__ void gemm_mainloop(
    const __half* __restrict__ gA, const __half* __restrict__ gB, int K,
    uint32_t sbase, float acc[2][8][4],
    int tid, int lane, int warpM, int warpN) {

    auto issue_loads = [&](int c, int s) {
        int k0 = c * BK;
        uint32_t st = sbase + s * STAGE_B;
#pragma unroll
        for (int j = 0; j < 4; j++) {
            int seg = tid + j * 256;
            int r = seg >> 3, cc = seg & 7;
            CP_ASYNC16(st + r * (PITCHH * 2) + cc * 16, gA + (size_t)r * K + k0 + cc * 8);
            CP_ASYNC16(st + TILE_B + r * (PITCHH * 2) + cc * 16, gB + (size_t)r * K + k0 + cc * 8);
        }
        CP_COMMIT();
    };

#pragma unroll
    for (int i = 0; i < 2; i++)
#pragma unroll
        for (int j = 0; j < 8; j++)
#pragma unroll
            for (int k = 0; k < 4; k++) acc[i][j][k] = 0.f;

    int a_r = warpM * 32 + (lane & 15);
    int a_c8 = (lane >> 4) << 3;
    int b_r = warpN * 64 + ((lane >> 4) << 3) + (lane & 7);
    int b_c8 = ((lane >> 3) & 1) << 3;

    auto compute = [&](int s) {
        uint32_t st = sbase + s * STAGE_B;
#pragma unroll
        for (int ki = 0; ki < 4; ki++) {
            uint32_t ah[2][4];
#pragma unroll
            for (int mi = 0; mi < 2; mi++) {
                uint32_t off = (uint32_t)((a_r + mi * 16) * (PITCHH * 2) + (ki * 16 + a_c8) * 2);
                LDSM4(ah[mi], st + off);
            }
            uint32_t bh[4][4];
#pragma unroll
            for (int nb = 0; nb < 4; nb++) {
                uint32_t off = (uint32_t)((b_r + nb * 16) * (PITCHH * 2) + (ki * 16 + b_c8) * 2);
                LDSM4(bh[nb], st + TILE_B + off);
            }
#pragma unroll
            for (int mi = 0; mi < 2; mi++)
#pragma unroll
                for (int nb = 0; nb < 4; nb++) {
                    MMA16816(acc[mi][2*nb],   ah[mi], bh[nb][0], bh[nb][1]);
                    MMA16816(acc[mi][2*nb+1], ah[mi], bh[nb][2], bh[nb][3]);
                }
        }
    };

    int nc = K / BK;
    issue_loads(0, 0);
    issue_loads(1, 1);
    for (int c = 0; c < nc; c++) {
        int s = c % NSTAGE;
        if (c + 1 < nc) { CP_WAIT1(); } else { CP_WAIT0(); }
        __syncthreads();
        if (c + 2 < nc) issue_loads(c + 2, (c + 2) % NSTAGE);
        compute(s);
    }
}

// ================= merged G1+G3 =================
__global__ void __launch_bounds__(256, 2) gemm_a(
    const __half* __restrict__ hs, const __half* __restrict__ wqa,
    const __half* __restrict__ wkva,
    float* __restrict__ qc, float* __restrict__ kvt) {
    GRID_SYNC();
    extern __shared__ char sm[];
    uint32_t sbase = smem_u32(sm);
    int tid = threadIdx.x, lane = tid & 31, wid = tid >> 5;
    int warpM = wid & 3, warpN = wid >> 2;
    int row0 = blockIdx.y * 128;
    int bx = blockIdx.x;

    const __half* B;
    float* C; int cN, col0, Nlim;
    if (bx < 12) { col0 = bx * 128;        B = wqa  + (size_t)col0 * HID; C = qc;  cN = QLORA; Nlim = QLORA; }
    else         { col0 = (bx - 12) * 128; B = wkva + (size_t)col0 * HID; C = kvt; cN = KVLORA+ROPED; Nlim = KVLORA+ROPED; }

    float acc[2][8][4];
    gemm_mainloop(hs + (size_t)row0 * HID, B, HID, sbase, acc, tid, lane, warpM, warpN);

    int g = lane >> 2, t = lane & 3;
#pragma unroll
    for (int mi = 0; mi < 2; mi++)
#pragma unroll
        for (int n8 = 0; n8 < 8; n8++) {
            int col = col0 + warpN * 64 + n8 * 8 + t * 2;
            if (col < Nlim) {
                int r0 = row0 + warpM * 32 + mi * 16 + g;
                float* p0 = C + (size_t)r0 * cN + col;
                p0[0] = acc[mi][n8][0]; p0[1] = acc[mi][n8][1];
                float* p1 = p0 + (size_t)8 * cN;
                p1[0] = acc[mi][n8][2]; p1[1] = acc[mi][n8][3];
            }
        }
}

// ================= merged G2+G4 =================
__global__ void __launch_bounds__(256, 2) gemm_b(
    const __half* __restrict__ qch, const __half* __restrict__ wqb,
    const __half* __restrict__ kvch, const __half* __restrict__ wkvb,
    const int* __restrict__ pos,
    __half* __restrict__ qfh, __half* __restrict__ kfh, __half* __restrict__ vfh) {
    GRID_SYNC();
    extern __shared__ char sm[];
    uint32_t sbase = smem_u32(sm);
    int tid = threadIdx.x, lane = tid & 31, wid = tid >> 5;
    int warpM = wid & 3, warpN = wid >> 2;
    int row0 = blockIdx.y * 128;
    int bx = blockIdx.x;
    int g = lane >> 2, t4 = lane & 3;

    if (bx < 24) {
        int col0 = bx * 128;
        float acc[2][8][4];
        gemm_mainloop(qch + (size_t)row0 * QLORA, wqb + (size_t)col0 * QLORA, QLORA,
                      sbase, acc, tid, lane, warpM, warpN);

        int colw = col0 + warpN * 64;
        int hH = colw / 192;
        int dbase = colw % 192;
        if (dbase != 128) {
#pragma unroll
            for (int mi = 0; mi < 2; mi++)
#pragma unroll
                for (int rr = 0; rr < 2; rr++) {
                    int row = row0 + warpM * 32 + mi * 16 + g + rr * 8;
                    int b = row >> 11, srow = row & 2047;
                    size_t obase = ((size_t)(b * NHh + hH) * Ss + srow) * QKD;
#pragma unroll
                    for (int n8 = 0; n8 < 8; n8++) {
                        int d = dbase + n8 * 8 + t4 * 2;
                        *(__half2*)(qfh + obase + d) = __floats2half2_rn(
                            acc[mi][n8][rr*2] * SCALEF, acc[mi][n8][rr*2+1] * SCALEF);
                    }
                }
        } else {
#pragma unroll
            for (int mi = 0; mi < 2; mi++)
#pragma unroll
                for (int rr = 0; rr < 2; rr++) {
                    int row = row0 + warpM * 32 + mi * 16 + g + rr * 8;
                    int b = row >> 11, srow = row & 2047;
                    float p = (float)pos[b * Ss + srow];
                    size_t obase = ((size_t)(b * NHh + hH) * Ss + srow) * QKD;
#pragma unroll
                    for (int n8 = 0; n8 < 4; n8++) {
                        int j0 = n8 * 8 + t4 * 2;
                        float if0 = __expf(-(float)j0 * (LN10K / 32.f));
                        float if1 = __expf(-(float)(j0 + 1) * (LN10K / 32.f));
                        float s0, c0, s1, c1;
                        __sincosf(p * if0, &s0, &c0);
                        __sincosf(p * if1, &s1, &c1);
                        float x1a = acc[mi][n8][rr*2],   x2a = acc[mi][n8+4][rr*2];
                        float x1b = acc[mi][n8][rr*2+1], x2b = acc[mi][n8+4][rr*2+1];
                        *(__half2*)(qfh + obase + 128 + j0) = __floats2half2_rn(
                            (x1a * c0 - x2a * s0) * SCALEF, (x1b * c1 - x2b * s1) * SCALEF);
                        *(__half2*)(qfh + obase + 160 + j0) = __floats2half2_rn(
                            (x2a * c0 + x1a * s0) * SCALEF, (x2b * c1 + x1b * s1) * SCALEF);
                    }
                }
        }
    } else {
        int col0 = (bx - 24) * 128;
        float acc[2][8][4];
        gemm_mainloop(kvch + (size_t)row0 * KVLORA, wkvb + (size_t)col0 * KVLORA, KVLORA,
                      sbase, acc, tid, lane, warpM, warpN);

        int hH = col0 >> 8;
        int isV = (col0 >> 7) & 1;
        __half* D = isV ? vfh : kfh;
        int stride = isV ? VDIM : QKD;
#pragma unroll
        for (int mi = 0; mi < 2; mi++)
#pragma unroll
            for (int n8 = 0; n8 < 8; n8++) {
                int col = col0 + warpN * 64 + n8 * 8 + t4 * 2;
                int d = col & 127;
#pragma unroll
                for (int rr = 0; rr < 2; rr++) {
                    int r0 = row0 + warpM * 32 + mi * 16 + g + rr * 8;
                    int b = r0 >> 11, srow = r0 & 2047;
                    size_t o = ((size_t)(b * NHh + hH) * Ss + srow) * stride + d;
                    *(__half2*)(D + o) = __floats2half2_rn(acc[mi][n8][rr*2], acc[mi][n8][rr*2+1]);
                }
            }
    }
}

// ================= G5 =================
__global__ void __launch_bounds__(256, 2) gemm_c(
    const __half* __restrict__ at, const __half* __restrict__ wo,
    float* __restrict__ out) {
    GRID_SYNC();
    extern __shared__ char sm[];
    uint32_t sbase = smem_u32(sm);
    int tid = threadIdx.x, lane = tid & 31, wid = tid >> 5;
    int warpM = wid & 3, warpN = wid >> 2;
    int row0 = blockIdx.y * 128, col0 = blockIdx.x * 128;

    float acc[2][8][4];
    gemm_mainloop(at + (size_t)row0 * HID, wo + (size_t)col0 * HID, HID,
                  sbase, acc, tid, lane, warpM, warpN);

    int g = lane >> 2, t = lane & 3;
#pragma unroll
    for (int mi = 0; mi < 2; mi++)
#pragma unroll
        for (int n8 = 0; n8 < 8; n8++) {
            int col = col0 + warpN * 64 + n8 * 8 + t * 2;
            int r0 = row0 + warpM * 32 + mi * 16 + g;
            float* p0 = out + (size_t)r0 * HID + col;
            p0[0] = acc[mi][n8][0]; p0[1] = acc[mi][n8][1];
            float* p1 = p0 + (size_t)8 * HID;
            p1[0] = acc[mi][n8][2]; p1[1] = acc[mi][n8][3];
        }
}

// ================= merged prep kernels =================
__device__ __forceinline__ void do_transpose(
    const float* __restrict__ W, __half* __restrict__ Th,
    int K, int srcN, int colTiles, int tile, int tid) {
    __shared__ float t[32][33];
    int n0 = (tile % colTiles) * 32, k0 = (tile / colTiles) * 32;
    int tx = tid & 31, ty = tid >> 5;
#pragma unroll
    for (int i = 0; i < 4; i++) {
        int k = k0 + ty + i * 8, n = n0 + tx;
        t[ty + i * 8][tx] = (n < srcN) ? W[(size_t)k * srcN + n] : 0.f;
    }
    __syncthreads();
#pragma unroll
    for (int i = 0; i < 4; i++) {
        int n = n0 + ty + i * 8;
        Th[(size_t)n * K + k0 + tx] = __float2half(t[tx][ty + i * 8]);
    }
}

__global__ void prep_main(const float* __restrict__ hs, __half* __restrict__ hsh,
                          const float* __restrict__ wqa, __half* __restrict__ wqah,
                          const float* __restrict__ wkva, __half* __restrict__ wkvah) {
    int bx = blockIdx.x, tid = threadIdx.x;
    if (bx < 4096) {
        size_t i = ((size_t)bx * 256 + tid) * 8;
        float4 v0 = *(const float4*)(hs + i);
        float4 v1 = *(const float4*)(hs + i + 4);
        *(__half2*)(hsh + i)     = __floats2half2_rn(v0.x, v0.y);
        *(__half2*)(hsh + i + 2) = __floats2half2_rn(v0.z, v0.w);
        *(__half2*)(hsh + i + 4) = __floats2half2_rn(v1.x, v1.y);
        *(__half2*)(hsh + i + 6) = __floats2half2_rn(v1.z, v1.w);
    } else if (bx < 4096 + 3072) {
        do_transpose(wqa, wqah, HID, QLORA, QLORA/32, bx - 4096, tid);
    } else {
        do_transpose(wkva, wkvah, HID, KVLORA+ROPED, WKVA_NPAD/32, bx - 7168, tid);
    }
}

__global__ void prep_aux(const float* __restrict__ wqb, __half* __restrict__ wqbh,
                         const float* __restrict__ wkvb, __half* __restrict__ wkvbh,
                         const float* __restrict__ wo, __half* __restrict__ woh) {
    int bx = blockIdx.x, tid = threadIdx.x;
    if (bx < 4608) {
        do_transpose(wqb, wqbh, QLORA, NHh*QKD, (NHh*QKD)/32, bx, tid);
    } else if (bx < 4608 + 2048) {
        do_transpose(wkvb, wkvbh, KVLORA, NHh*(NOPE+VDIM), (NHh*(NOPE+VDIM))/32, bx - 4608, tid);
    } else {
        do_transpose(wo, woh, NHh*VDIM, HID, HID/32, bx - 6656, tid);
    }
}

// ================= register-resident single-pass norm =================
__device__ __forceinline__ float block_reduce_sum(float v, float* red8, int tid) {
#pragma unroll
    for (int off = 16; off > 0; off >>= 1)
        v += __shfl_xor_sync(0xffffffffu, v, off);
    if ((tid & 31) == 0) red8[tid >> 5] = v;
    __syncthreads();
    float s = (tid < 8) ? red8[tid] : 0.f;
#pragma unroll
    for (int off = 4; off > 0; off >>= 1)
        s += __shfl_xor_sync(0xffffffffu, s, off);
    if (tid == 0) red8[0] = s;
    __syncthreads();
    return red8[0];
}

__global__ void norm_fused(const float* __restrict__ qc, const float* __restrict__ qw,
                           const float* __restrict__ kvt, const float* __restrict__ kvw,
                           const int* __restrict__ pos,
                           __half* __restrict__ qch, __half* __restrict__ kvch,
                           __half* __restrict__ kfh) {
    GRID_SYNC();
    __shared__ float red8[8];
    __shared__ float rop[64];
    int tid = threadIdx.x;
    if (blockIdx.x < ROWS) {
        int row = blockIdx.x;
        const float* r = qc + (size_t)row * QLORA;
        float4 v4 = *(const float4*)(r + 4 * tid);
        float2 v2 = *(const float2*)(r + 1024 + 2 * tid);
        float ss = v4.x*v4.x + v4.y*v4.y + v4.z*v4.z + v4.w*v4.w + v2.x*v2.x + v2.y*v2.y;
        float tot = block_reduce_sum(ss, red8, tid);
        float scale = rsqrtf(tot / (float)QLORA + 1e-6f);
        float4 w4 = *(const float4*)(qw + 4 * tid);
        float2 w2 = *(const float2*)(qw + 1024 + 2 * tid);
        __half* o = qch + (size_t)row * QLORA;
        *(__half2*)(o + 4*tid)        = __floats2half2_rn(v4.x*scale*w4.x, v4.y*scale*w4.y);
        *(__half2*)(o + 4*tid + 2)    = __floats2half2_rn(v4.z*scale*w4.z, v4.w*scale*w4.w);
        *(__half2*)(o + 1024 + 2*tid) = __floats2half2_rn(v2.x*scale*w2.x, v2.y*scale*w2.y);
    } else {
        int row = blockIdx.x - ROWS;
        const float* r = kvt + (size_t)row * (KVLORA + ROPED);
        float2 v2 = *(const float2*)(r + 2 * tid);
        float ss = v2.x*v2.x + v2.y*v2.y;
        if (tid < 32) {
            float p = (float)pos[row];
            float inv_freq = __expf(-(float)tid * (LN10K / 32.f));
            float c, s;
            __sincosf(p * inv_freq, &s, &c);
            float x1 = r[KVLORA + tid];
            float x2 = r[KVLORA + 32 + tid];
            rop[tid]      = x1 * c - x2 * s;
            rop[tid + 32] = x2 * c + x1 * s;
        }
        float tot = block_reduce_sum(ss, red8, tid);
        float scale = rsqrtf(tot / (float)KVLORA + 1e-6f);
        float2 w2 = *(const float2*)(kvw + 2 * tid);
        *(__half2*)(kvch + (size_t)row * KVLORA + 2*tid) =
            __floats2half2_rn(v2.x*scale*w2.x, v2.y*scale*w2.y);
        int b = row >> 11, srow = row & 2047;
        for (int e = tid; e < NHh * ROPED; e += 256) {
            int h = e >> 6, d = e & 63;
            size_t o = ((size_t)(b * NHh + h) * Ss + srow) * QKD + NOPE + d;
            kfh[o] = __float2half(rop[d]);
        }
    }
}

// ================= fp16 flash v3 (R13): kv-tile 64, Q in registers ==========
#define FQ_PITCH 400
#define FV_PITCH 272
#define FQ_SZ    (128*FQ_PITCH)           // 51200
#define FK_SZ    (64*FQ_PITCH)            // 25600
#define FV_SZ    (64*FV_PITCH)            // 17408
#define F_OFF_K  FQ_SZ
#define F_OFF_V  (F_OFF_K + 2*FK_SZ)      // 102400
#define FLASH_SMEM (F_OFF_V + 2*FV_SZ)    // 137216

__global__ void __launch_bounds__(256, 1) flash_mma(
    const __half* __restrict__ qh, const __half* __restrict__ kh,
    const __half* __restrict__ vh, __half* __restrict__ oh) {
    GRID_SYNC();
    extern __shared__ char sm[];
    uint32_t sb = smem_u32(sm);

    int qt = (gridDim.x - 1) - blockIdx.x;
    int h = blockIdx.y, b = blockIdx.z;
    int q0 = qt * 128;
    int tid = threadIdx.x, lane = tid & 31, w = tid >> 5;
    int bh = b * NHh + h;

    const __half* qhb = qh + ((size_t)bh * Ss + q0) * QKD;
    const __half* khb = kh + (size_t)bh * Ss * QKD;
    const __half* vhb = vh + (size_t)bh * Ss * VDIM;

#pragma unroll
    for (int i = 0; i < 12; i++) {
        int e = tid + i * 256;
        int r = e / 24, c = e % 24;
        CP_ASYNC16(sb + r * FQ_PITCH + c * 16, qhb + (size_t)r * QKD + c * 8);
    }
    CP_COMMIT();

    auto load_kv = [&](int kt, int s) {
        int k0 = kt * 64;
        uint32_t kst = sb + F_OFF_K + s * FK_SZ;
        uint32_t vst = sb + F_OFF_V + s * FV_SZ;
#pragma unroll
        for (int i = 0; i < 6; i++) {
            int e = tid + i * 256;
            int r = e / 24, c = e % 24;
            CP_ASYNC16(kst + r * FQ_PITCH + c * 16, khb + (size_t)(k0 + r) * QKD + c * 8);
        }
#pragma unroll
        for (int i = 0; i < 4; i++) {
            int e = tid + i * 256;
            int r = e >> 4, c = e & 15;
            CP_ASYNC16(vst + r * FV_PITCH + c * 16, vhb + (size_t)(k0 + r) * VDIM + c * 8);
        }
        CP_COMMIT();
    };

    load_kv(0, 0);

    int a_r = w * 16 + (lane & 15);
    int a_c8 = (lane >> 4) << 3;
    int b_r = ((lane >> 4) << 3) + (lane & 7);
    int b_c8 = ((lane >> 3) & 1) << 3;
    int vt_r = lane & 15;
    int vt_c8 = (lane >> 4) << 3;

    int g = lane >> 2, t4 = lane & 3;

    CP_WAIT1();
    __syncthreads();
    uint32_t qfr[12][4];
#pragma unroll
    for (int kk = 0; kk < 12; kk++)
        LDSM4(qfr[kk], sb + (uint32_t)(a_r * FQ_PITCH + (kk * 16 + a_c8) * 2));

    float m0 = -INFINITY, m1 = -INFINITY, l0 = 0.f, l1 = 0.f;
    float O[16][4];
#pragma unroll
    for (int j = 0; j < 16; j++)
#pragma unroll
        for (int k = 0; k < 4; k++) O[j][k] = 0.f;

    int qrow0 = q0 + w * 16 + g;
    int qrow1 = qrow0 + 8;

    int nkt = (q0 + 128) >> 6;

    for (int kt = 0; kt < nkt; kt++) {
        int s = kt & 1;
        if (kt + 1 < nkt) { load_kv(kt + 1, s ^ 1); CP_WAIT1(); }
        else              { CP_WAIT0(); }
        __syncthreads();

        uint32_t kst = sb + F_OFF_K + s * FK_SZ;
        uint32_t vst = sb + F_OFF_V + s * FV_SZ;
        int k0 = kt * 64;

        float sc[8][4];
#pragma unroll
        for (int j = 0; j < 8; j++)
#pragma unroll
            for (int k = 0; k < 4; k++) sc[j][k] = 0.f;

#pragma unroll
        for (int kk = 0; kk < 12; kk++) {
#pragma unroll
            for (int nb = 0; nb < 4; nb++) {
                uint32_t bhf[4];
                LDSM4(bhf, kst + (uint32_t)((nb * 16 + b_r) * FQ_PITCH + (kk * 16 + b_c8) * 2));
                MMA16816(sc[2*nb],   qfr[kk], bhf[0], bhf[1]);
                MMA16816(sc[2*nb+1], qfr[kk], bhf[2], bhf[3]);
            }
        }

        if (k0 + 63 > q0) {
#pragma unroll
            for (int j = 0; j < 8; j++) {
                int col = k0 + j * 8 + t4 * 2;
                if (col     > qrow0) sc[j][0] = -INFINITY;
                if (col + 1 > qrow0) sc[j][1] = -INFINITY;
                if (col     > qrow1) sc[j][2] = -INFINITY;
                if (col + 1 > qrow1) sc[j][3] = -INFINITY;
            }
        }

        float rm0 = -INFINITY, rm1 = -INFINITY;
#pragma unroll
        for (int j = 0; j < 8; j++) {
            rm0 = fmaxf(rm0, fmaxf(sc[j][0], sc[j][1]));
            rm1 = fmaxf(rm1, fmaxf(sc[j][2], sc[j][3]));
        }
        rm0 = fmaxf(rm0, __shfl_xor_sync(0xffffffffu, rm0, 1));
        rm0 = fmaxf(rm0, __shfl_xor_sync(0xffffffffu, rm0, 2));
        rm1 = fmaxf(rm1, __shfl_xor_sync(0xffffffffu, rm1, 1));
        rm1 = fmaxf(rm1, __shfl_xor_sync(0xffffffffu, rm1, 2));
        float nm0 = fmaxf(m0, rm0), nm1 = fmaxf(m1, rm1);
        float rs0 = 0.f, rs1 = 0.f;
#pragma unroll
        for (int j = 0; j < 8; j++) {
            sc[j][0] = __expf(sc[j][0] - nm0);
            sc[j][1] = __expf(sc[j][1] - nm0);
            sc[j][2] = __expf(sc[j][2] - nm1);
            sc[j][3] = __expf(sc[j][3] - nm1);
            rs0 += sc[j][0] + sc[j][1];
            rs1 += sc[j][2] + sc[j][3];
        }
        rs0 += __shfl_xor_sync(0xffffffffu, rs0, 1);
        rs0 += __shfl_xor_sync(0xffffffffu, rs0, 2);
        rs1 += __shfl_xor_sync(0xffffffffu, rs1, 1);
        rs1 += __shfl_xor_sync(0xffffffffu, rs1, 2);
        float al0 = __expf(m0 - nm0), al1 = __expf(m1 - nm1);
        l0 = l0 * al0 + rs0; l1 = l1 * al1 + rs1;
        m0 = nm0; m1 = nm1;
#pragma unroll
        for (int j = 0; j < 16; j++) {
            O[j][0] *= al0; O[j][1] *= al0;
            O[j][2] *= al1; O[j][3] *= al1;
        }

        uint32_t ph2[8][2];
#pragma unroll
        for (int j = 0; j < 8; j++) {
            __half2 p01 = __floats2half2_rn(sc[j][0], sc[j][1]);
            __half2 p23 = __floats2half2_rn(sc[j][2], sc[j][3]);
            ph2[j][0] = *(uint32_t*)&p01;
            ph2[j][1] = *(uint32_t*)&p23;
        }

#pragma unroll
        for (int kk = 0; kk < 4; kk++) {
            uint32_t ah[4] = { ph2[2*kk][0], ph2[2*kk][1], ph2[2*kk+1][0], ph2[2*kk+1][1] };
#pragma unroll
            for (int j2 = 0; j2 < 8; j2++) {
                uint32_t vhf[4];
                LDSM4T(vhf, vst + (uint32_t)((kk * 16 + vt_r) * FV_PITCH + (j2 * 16 + vt_c8) * 2));
                MMA16816(O[2*j2],   ah, vhf[0], vhf[1]);
                MMA16816(O[2*j2+1], ah, vhf[2], vhf[3]);
            }
        }
        __syncthreads();
    }

    float inv0 = 1.f / l0, inv1 = 1.f / l1;
    size_t ob0 = ((size_t)(b * Ss + qrow0)) * (NHh * VDIM) + h * VDIM;
    size_t ob1 = ((size_t)(b * Ss + qrow1)) * (NHh * VDIM) + h * VDIM;
#pragma unroll
    for (int j = 0; j < 16; j++) {
        int d = j * 8 + t4 * 2;
        *(__half2*)(oh + ob0 + d) = __floats2half2_rn(O[j][0] * inv0, O[j][1] * inv0);
        *(__half2*)(oh + ob1 + d) = __floats2half2_rn(O[j][2] * inv1, O[j][3] * inv1);
    }
}

// ================= launch =================
extern "C" void kernel_launch(void* const* d_in, const int* in_sizes, int n_in,
                              void* d_out, int out_size) {
    const float* hs     = (const float*)d_in[0];
    const int*   pos    = (const int*)  d_in[1];
    const float* w_q_a  = (const float*)d_in[3];
    const float* q_ln   = (const float*)d_in[4];
    const float* w_q_b  = (const float*)d_in[5];
    const float* w_kv_a = (const float*)d_in[6];
    const float* kv_ln  = (const float*)d_in[7];
    const float* w_kv_b = (const float*)d_in[8];
    const float* w_o    = (const float*)d_in[9];
    float* out = (float*)d_out;

    float *qc, *kvt;
    cudaGetSymbolAddress((void**)&qc,  g_qc);
    cudaGetSymbolAddress((void**)&kvt, g_kvt);

    __half *hs_h,*qc_h,*kvc_h,*at_h;
    __half *wqa_h,*wqb_h,*wkva_h,*wkvb_h,*wo_h;
    __half *qfh,*kfh,*vfh;
    cudaGetSymbolAddress((void**)&hs_h,  g_hs_h);
    cudaGetSymbolAddress((void**)&qc_h,  g_qc_h);
    cudaGetSymbolAddress((void**)&kvc_h, g_kvc_h);
    cudaGetSymbolAddress((void**)&at_h,  g_at_h);
    cudaGetSymbolAddress((void**)&wqa_h, g_wqa_h);
    cudaGetSymbolAddress((void**)&wqb_h, g_wqb_h);
    cudaGetSymbolAddress((void**)&wkva_h,g_wkva_h);
    cudaGetSymbolAddress((void**)&wkvb_h,g_wkvb_h);
    cudaGetSymbolAddress((void**)&wo_h,  g_wo_h);
    cudaGetSymbolAddress((void**)&qfh,   g_qfh);
    cudaGetSymbolAddress((void**)&kfh,   g_kfh);
    cudaGetSymbolAddress((void**)&vfh,   g_vfh);

    cudaFuncSetAttribute(gemm_a, cudaFuncAttributeMaxDynamicSharedMemorySize, GEMM_SMEM);
    cudaFuncSetAttribute(gemm_b, cudaFuncAttributeMaxDynamicSharedMemorySize, GEMM_SMEM);
    cudaFuncSetAttribute(gemm_c, cudaFuncAttributeMaxDynamicSharedMemorySize, GEMM_SMEM);
    cudaFuncSetAttribute(flash_mma, cudaFuncAttributeMaxDynamicSharedMemorySize, FLASH_SMEM);

    cudaStream_t s2;
    cudaStreamCreateWithFlags(&s2, cudaStreamNonBlocking);
    cudaEvent_t evFork, evJoin;
    cudaEventCreateWithFlags(&evFork, cudaEventDisableTiming);
    cudaEventCreateWithFlags(&evJoin, cudaEventDisableTiming);

    cudaEventRecord(evFork, 0);
    cudaStreamWaitEvent(s2, evFork, 0);
    prep_aux<<<4608 + 2048 + 4096, 256, 0, s2>>>(w_q_b, wqb_h, w_kv_b, wkvb_h, w_o, wo_h);
    cudaEventRecord(evJoin, s2);

    prep_main<<<4096 + 3072 + 1280, 256>>>(hs, hs_h, w_q_a, wqa_h, w_kv_a, wkva_h);

    cudaLaunchAttribute pdlAttr[1];
    pdlAttr[0].id = cudaLaunchAttributeProgrammaticStreamSerialization;
    pdlAttr[0].val.programmaticStreamSerializationAllowed = 1;

    {
        cudaLaunchConfig_t cfg{};
        cfg.gridDim = dim3(12 + WKVA_NPAD/128, ROWS/128);
        cfg.blockDim = dim3(256);
        cfg.dynamicSmemBytes = GEMM_SMEM;
        cfg.stream = 0; cfg.attrs = pdlAttr; cfg.numAttrs = 1;
        cudaLaunchKernelEx(&cfg, gemm_a, hs_h, wqa_h, wkva_h, qc, kvt);
    }
    {
        cudaLaunchConfig_t cfg{};
        cfg.gridDim = dim3(2*ROWS);
        cfg.blockDim = dim3(256);
        cfg.dynamicSmemBytes = 0;
        cfg.stream = 0; cfg.attrs = pdlAttr; cfg.numAttrs = 1;
        cudaLaunchKernelEx(&cfg, norm_fused, (const float*)qc, q_ln, (const float*)kvt, kv_ln,
                           pos, qc_h, kvc_h, kfh);
    }

    cudaStreamWaitEvent(0, evJoin, 0);

    {
        cudaLaunchConfig_t cfg{};
        cfg.gridDim = dim3(24 + 32, ROWS/128);
        cfg.blockDim = dim3(256);
        cfg.dynamicSmemBytes = GEMM_SMEM;
        cfg.stream = 0; cfg.attrs = pdlAttr; cfg.numAttrs = 1;
        cudaLaunchKernelEx(&cfg, gemm_b, (const __half*)qc_h, (const __half*)wqb_h,
                           (const __half*)kvc_h, (const __half*)wkvb_h, pos, qfh, kfh, vfh);
    }
    {
        cudaLaunchConfig_t cfg{};
        cfg.gridDim = dim3(Ss/128, NHh, Bb);
        cfg.blockDim = dim3(256);
        cfg.dynamicSmemBytes = FLASH_SMEM;
        cfg.stream = 0; cfg.attrs = pdlAttr; cfg.numAttrs = 1;
        cudaLaunchKernelEx(&cfg, flash_mma, (const __half*)qfh, (const __half*)kfh,
                           (const __half*)vfh, at_h);
    }
    {
        cudaLaunchConfig_t cfg{};
        cfg.gridDim = dim3(HID/128, ROWS/128);
        cfg.blockDim = dim3(256);
        cfg.dynamicSmemBytes = GEMM_SMEM;
        cfg.stream = 0; cfg.attrs = pdlAttr; cfg.numAttrs = 1;
        cudaLaunchKernelEx(&cfg, gemm_c, (const __half*)at_h, (const __half*)wo_h, out);
    }

    cudaEventDestroy(evFork);
    cudaEventDestroy(evJoin);
    cudaStreamDestroy(s2);
}

// round 16
// speedup vs baseline: 1.0228x; 1.0102x over previous
#include <cuda_runtime.h>
#include <cuda_fp16.h>
#include <math.h>
#include <cstdint>

// ---------------- problem constants ----------------
#define Bb   2
#define Ss   2048
#define HID  2048
#define NHh  16
#define QLORA 1536
#define KVLORA 512
#define NOPE 128
#define ROPED 64
#define VDIM 128
#define QKD  192
#define ROWS (Bb*Ss)          // 4096
#define WKVA_NPAD 640
#define SCALEF 0.07216878364870322f
#define LN10K  9.210340371976184f

// ---------------- fp32 scratch ----------------
__device__ float g_qc   [(size_t)ROWS * QLORA];
__device__ float g_kvt  [(size_t)ROWS * (KVLORA+ROPED)];

// ---------------- fp16 activations ----------------
__device__ __half g_hs_h [(size_t)ROWS*HID];
__device__ __half g_qc_h [(size_t)ROWS*QLORA];
__device__ __half g_kvc_h[(size_t)ROWS*KVLORA];
__device__ __half g_at_h [(size_t)ROWS*NHh*VDIM];

// ---------------- fp16 transposed weights [N,K] ----------------
__device__ __half g_wqa_h [(size_t)QLORA*HID];
__device__ __half g_wqb_h [(size_t)(NHh*QKD)*QLORA];
__device__ __half g_wkva_h[(size_t)WKVA_NPAD*HID];
__device__ __half g_wkvb_h[(size_t)(NHh*(NOPE+VDIM))*KVLORA];
__device__ __half g_wo_h  [(size_t)HID*(NHh*VDIM)];

// ---------------- flash fp16 buffers, [b,h,s,d] ----------------
__device__ __half g_qfh[(size_t)ROWS*NHh*QKD];
__device__ __half g_kfh[(size_t)ROWS*NHh*QKD];
__device__ __half g_vfh[(size_t)ROWS*NHh*VDIM];

// ================= helpers =================
__device__ __forceinline__ uint32_t smem_u32(const void* p) {
    uint32_t a;
    asm("{ .reg .u64 t; cvta.to.shared.u64 t, %1; cvt.u32.u64 %0, t; }" : "=r"(a) : "l"(p));
    return a;
}

#define LDSM4(r, a) asm volatile( \
    "ldmatrix.sync.aligned.m8n8.x4.shared.b16 {%0,%1,%2,%3}, [%4];" \
    : "=r"((r)[0]),"=r"((r)[1]),"=r"((r)[2]),"=r"((r)[3]) : "r"(a))

#define LDSM4T(r, a) asm volatile( \
    "ldmatrix.sync.aligned.m8n8.x4.trans.shared.b16 {%0,%1,%2,%3}, [%4];" \
    : "=r"((r)[0]),"=r"((r)[1]),"=r"((r)[2]),"=r"((r)[3]) : "r"(a))

#define MMA16816(d, a, b0v, b1v) asm volatile( \
    "mma.sync.aligned.m16n8k16.row.col.f32.f16.f16.f32 " \
    "{%0,%1,%2,%3},{%4,%5,%6,%7},{%8,%9},{%0,%1,%2,%3};" \
    : "+f"((d)[0]),"+f"((d)[1]),"+f"((d)[2]),"+f"((d)[3]) \
    : "r"((a)[0]),"r"((a)[1]),"r"((a)[2]),"r"((a)[3]), "r"(b0v),"r"(b1v))

#define CP_ASYNC16(sa, ga) asm volatile( \
    "cp.async.cg.shared.global [%0], [%1], 16;" :: "r"(sa), "l"(ga))
#define CP_COMMIT() asm volatile("cp.async.commit_group;" ::: "memory")
#define CP_WAIT1()  asm volatile("cp.async.wait_group 1;" ::: "memory")
#define CP_WAIT0()  asm volatile("cp.async.wait_group 0;" ::: "memory")

#define GRID_SYNC() cudaGridDependencySynchronize()

// ================= fp16 HMMA GEMM mainloop, BK=64 (unchanged R15) ==========
#define BK 64
#define PITCHH 72
#define TILE_B (128*PITCHH*2)          // 18432
#define STAGE_B (2*TILE_B)             // 36864
#define NSTAGE 3
#define GEMM_SMEM (NSTAGE*STAGE_B)     // 110592

__device__ __forceinline__ void gemm_mainloop(
    const __half* __restrict__ gA, const __half* __restrict__ gB, int K,
    uint32_t sbase, float acc[2][8][4],
    int tid, int lane, int warpM, int warpN) {

    auto issue_loads = [&](int c, int s) {
        int k0 = c * BK;
        uint32_t st = sbase + s * STAGE_B;
#pragma unroll
        for (int j = 0; j < 4; j++) {
            int seg = tid + j * 256;
            int r = seg >> 3, cc = seg & 7;
            CP_ASYNC16(st + r * (PITCHH * 2) + cc * 16, gA + (size_t)r * K + k0 + cc * 8);
            CP_ASYNC16(st + TILE_B + r * (PITCHH * 2) + cc * 16, gB + (size_t)r * K + k0 + cc * 8);
        }
        CP_COMMIT();
    };

#pragma unroll
    for (int i = 0; i < 2; i++)
#pragma unroll
        for (int j = 0; j < 8; j++)
#pragma unroll
            for (int k = 0; k < 4; k++) acc[i][j][k] = 0.f;

    int a_r = warpM * 32 + (lane & 15);
    int a_c8 = (lane >> 4) << 3;
    int b_r = warpN * 64 + ((lane >> 4) << 3) + (lane & 7);
    int b_c8 = ((lane >> 3) & 1) << 3;

    auto compute = [&](int s) {
        uint32_t st = sbase + s * STAGE_B;
#pragma unroll
        for (int ki = 0; ki < 4; ki++) {
            uint32_t ah[2][4];
#pragma unroll
            for (int mi = 0; mi < 2; mi++) {
                uint32_t off = (uint32_t)((a_r + mi * 16) * (PITCHH * 2) + (ki * 16 + a_c8) * 2);
                LDSM4(ah[mi], st + off);
            }
            uint32_t bh[4][4];
#pragma unroll
            for (int nb = 0; nb < 4; nb++) {
                uint32_t off = (uint32_t)((b_r + nb * 16) * (PITCHH * 2) + (ki * 16 + b_c8) * 2);
                LDSM4(bh[nb], st + TILE_B + off);
            }
#pragma unroll
            for (int mi = 0; mi < 2; mi++)
#pragma unroll
                for (int nb = 0; nb < 4; nb++) {
                    MMA16816(acc[mi][2*nb],   ah[mi], bh[nb][0], bh[nb][1]);
                    MMA16816(acc[mi][2*nb+1], ah[mi], bh[nb][2], bh[nb][3]);
                }
        }
    };

    int nc = K / BK;
    issue_loads(0, 0);
    issue_loads(1, 1);
    for (int c = 0; c < nc; c++) {
        int s = c % NSTAGE;
        if (c + 1 < nc) { CP_WAIT1(); } else { CP_WAIT0(); }
        __syncthreads();
        if (c + 2 < nc) issue_loads(c + 2, (c + 2) % NSTAGE);
        compute(s);
    }
}

// ================= merged G1+G3 =================
__global__ void __launch_bounds__(256, 2) gemm_a(
    const __half* __restrict__ hs, const __half* __restrict__ wqa,
    const __half* __restrict__ wkva,
    float* __restrict__ qc, float* __restrict__ kvt) {
    GRID_SYNC();
    extern __shared__ char sm[];
    uint32_t sbase = smem_u32(sm);
    int tid = threadIdx.x, lane = tid & 31, wid = tid >> 5;
    int warpM = wid & 3, warpN = wid >> 2;
    int row0 = blockIdx.y * 128;
    int bx = blockIdx.x;

    const __half* B;
    float* C; int cN, col0, Nlim;
    if (bx < 12) { col0 = bx * 128;        B = wqa  + (size_t)col0 * HID; C = qc;  cN = QLORA; Nlim = QLORA; }
    else         { col0 = (bx - 12) * 128; B = wkva + (size_t)col0 * HID; C = kvt; cN = KVLORA+ROPED; Nlim = KVLORA+ROPED; }

    float acc[2][8][4];
    gemm_mainloop(hs + (size_t)row0 * HID, B, HID, sbase, acc, tid, lane, warpM, warpN);

    int g = lane >> 2, t = lane & 3;
#pragma unroll
    for (int mi = 0; mi < 2; mi++)
#pragma unroll
        for (int n8 = 0; n8 < 8; n8++) {
            int col = col0 + warpN * 64 + n8 * 8 + t * 2;
            if (col < Nlim) {
                int r0 = row0 + warpM * 32 + mi * 16 + g;
                float* p0 = C + (size_t)r0 * cN + col;
                p0[0] = acc[mi][n8][0]; p0[1] = acc[mi][n8][1];
                float* p1 = p0 + (size_t)8 * cN;
                p1[0] = acc[mi][n8][2]; p1[1] = acc[mi][n8][3];
            }
        }
}

// ================= merged G2+G4 =================
__global__ void __launch_bounds__(256, 2) gemm_b(
    const __half* __restrict__ qch, const __half* __restrict__ wqb,
    const __half* __restrict__ kvch, const __half* __restrict__ wkvb,
    const int* __restrict__ pos,
    __half* __restrict__ qfh, __half* __restrict__ kfh, __half* __restrict__ vfh) {
    GRID_SYNC();
    extern __shared__ char sm[];
    uint32_t sbase = smem_u32(sm);
    int tid = threadIdx.x, lane = tid & 31, wid = tid >> 5;
    int warpM = wid & 3, warpN = wid >> 2;
    int row0 = blockIdx.y * 128;
    int bx = blockIdx.x;
    int g = lane >> 2, t4 = lane & 3;

    if (bx < 24) {
        int col0 = bx * 128;
        float acc[2][8][4];
        gemm_mainloop(qch + (size_t)row0 * QLORA, wqb + (size_t)col0 * QLORA, QLORA,
                      sbase, acc, tid, lane, warpM, warpN);

        int colw = col0 + warpN * 64;
        int hH = colw / 192;
        int dbase = colw % 192;
        if (dbase != 128) {
#pragma unroll
            for (int mi = 0; mi < 2; mi++)
#pragma unroll
                for (int rr = 0; rr < 2; rr++) {
                    int row = row0 + warpM * 32 + mi * 16 + g + rr * 8;
                    int b = row >> 11, srow = row & 2047;
                    size_t obase = ((size_t)(b * NHh + hH) * Ss + srow) * QKD;
#pragma unroll
                    for (int n8 = 0; n8 < 8; n8++) {
                        int d = dbase + n8 * 8 + t4 * 2;
                        *(__half2*)(qfh + obase + d) = __floats2half2_rn(
                            acc[mi][n8][rr*2] * SCALEF, acc[mi][n8][rr*2+1] * SCALEF);
                    }
                }
        } else {
#pragma unroll
            for (int mi = 0; mi < 2; mi++)
#pragma unroll
                for (int rr = 0; rr < 2; rr++) {
                    int row = row0 + warpM * 32 + mi * 16 + g + rr * 8;
                    int b = row >> 11, srow = row & 2047;
                    float p = (float)pos[b * Ss + srow];
                    size_t obase = ((size_t)(b * NHh + hH) * Ss + srow) * QKD;
#pragma unroll
                    for (int n8 = 0; n8 < 4; n8++) {
                        int j0 = n8 * 8 + t4 * 2;
                        float if0 = __expf(-(float)j0 * (LN10K / 32.f));
                        float if1 = __expf(-(float)(j0 + 1) * (LN10K / 32.f));
                        float s0, c0, s1, c1;
                        __sincosf(p * if0, &s0, &c0);
                        __sincosf(p * if1, &s1, &c1);
                        float x1a = acc[mi][n8][rr*2],   x2a = acc[mi][n8+4][rr*2];
                        float x1b = acc[mi][n8][rr*2+1], x2b = acc[mi][n8+4][rr*2+1];
                        *(__half2*)(qfh + obase + 128 + j0) = __floats2half2_rn(
                            (x1a * c0 - x2a * s0) * SCALEF, (x1b * c1 - x2b * s1) * SCALEF);
                        *(__half2*)(qfh + obase + 160 + j0) = __floats2half2_rn(
                            (x2a * c0 + x1a * s0) * SCALEF, (x2b * c1 + x1b * s1) * SCALEF);
                    }
                }
        }
    } else {
        int col0 = (bx - 24) * 128;
        float acc[2][8][4];
        gemm_mainloop(kvch + (size_t)row0 * KVLORA, wkvb + (size_t)col0 * KVLORA, KVLORA,
                      sbase, acc, tid, lane, warpM, warpN);

        int hH = col0 >> 8;
        int isV = (col0 >> 7) & 1;
        __half* D = isV ? vfh : kfh;
        int stride = isV ? VDIM : QKD;
#pragma unroll
        for (int mi = 0; mi < 2; mi++)
#pragma unroll
            for (int n8 = 0; n8 < 8; n8++) {
                int col = col0 + warpN * 64 + n8 * 8 + t4 * 2;
                int d = col & 127;
#pragma unroll
                for (int rr = 0; rr < 2; rr++) {
                    int r0 = row0 + warpM * 32 + mi * 16 + g + rr * 8;
                    int b = r0 >> 11, srow = r0 & 2047;
                    size_t o = ((size_t)(b * NHh + hH) * Ss + srow) * stride + d;
                    *(__half2*)(D + o) = __floats2half2_rn(acc[mi][n8][rr*2], acc[mi][n8][rr*2+1]);
                }
            }
    }
}

// ================= G5 =================
__global__ void __launch_bounds__(256, 2) gemm_c(
    const __half* __restrict__ at, const __half* __restrict__ wo,
    float* __restrict__ out) {
    GRID_SYNC();
    extern __shared__ char sm[];
    uint32_t sbase = smem_u32(sm);
    int tid = threadIdx.x, lane = tid & 31, wid = tid >> 5;
    int warpM = wid & 3, warpN = wid >> 2;
    int row0 = blockIdx.y * 128, col0 = blockIdx.x * 128;

    float acc[2][8][4];
    gemm_mainloop(at + (size_t)row0 * HID, wo + (size_t)col0 * HID, HID,
                  sbase, acc, tid, lane, warpM, warpN);

    int g = lane >> 2, t = lane & 3;
#pragma unroll
    for (int mi = 0; mi < 2; mi++)
#pragma unroll
        for (int n8 = 0; n8 < 8; n8++) {
            int col = col0 + warpN * 64 + n8 * 8 + t * 2;
            int r0 = row0 + warpM * 32 + mi * 16 + g;
            float* p0 = out + (size_t)r0 * HID + col;
            p0[0] = acc[mi][n8][0]; p0[1] = acc[mi][n8][1];
            float* p1 = p0 + (size_t)8 * HID;
            p1[0] = acc[mi][n8][2]; p1[1] = acc[mi][n8][3];
        }
}

// ================= merged prep kernels =================
__device__ __forceinline__ void do_transpose(
    const float* __restrict__ W, __half* __restrict__ Th,
    int K, int srcN, int colTiles, int tile, int tid) {
    __shared__ float t[32][33];
    int n0 = (tile % colTiles) * 32, k0 = (tile / colTiles) * 32;
    int tx = tid & 31, ty = tid >> 5;
#pragma unroll
    for (int i = 0; i < 4; i++) {
        int k = k0 + ty + i * 8, n = n0 + tx;
        t[ty + i * 8][tx] = (n < srcN) ? W[(size_t)k * srcN + n] : 0.f;
    }
    __syncthreads();
#pragma unroll
    for (int i = 0; i < 4; i++) {
        int n = n0 + ty + i * 8;
        Th[(size_t)n * K + k0 + tx] = __float2half(t[tx][ty + i * 8]);
    }
}

__global__ void prep_main(const float* __restrict__ hs, __half* __restrict__ hsh,
                          const float* __restrict__ wqa, __half* __restrict__ wqah,
                          const float* __restrict__ wkva, __half* __restrict__ wkvah) {
    int bx = blockIdx.x, tid = threadIdx.x;
    if (bx < 4096) {
        size_t i = ((size_t)bx * 256 + tid) * 8;
        float4 v0 = *(const float4*)(hs + i);
        float4 v1 = *(const float4*)(hs + i + 4);
        *(__half2*)(hsh + i)     = __floats2half2_rn(v0.x, v0.y);
        *(__half2*)(hsh + i + 2) = __floats2half2_rn(v0.z, v0.w);
        *(__half2*)(hsh + i + 4) = __floats2half2_rn(v1.x, v1.y);
        *(__half2*)(hsh + i + 6) = __floats2half2_rn(v1.z, v1.w);
    } else if (bx < 4096 + 3072) {
        do_transpose(wqa, wqah, HID, QLORA, QLORA/32, bx - 4096, tid);
    } else {
        do_transpose(wkva, wkvah, HID, KVLORA+ROPED, WKVA_NPAD/32, bx - 7168, tid);
    }
}

__global__ void prep_aux(const float* __restrict__ wqb, __half* __restrict__ wqbh,
                         const float* __restrict__ wkvb, __half* __restrict__ wkvbh,
                         const float* __restrict__ wo, __half* __restrict__ woh) {
    int bx = blockIdx.x, tid = threadIdx.x;
    if (bx < 4608) {
        do_transpose(wqb, wqbh, QLORA, NHh*QKD, (NHh*QKD)/32, bx, tid);
    } else if (bx < 4608 + 2048) {
        do_transpose(wkvb, wkvbh, KVLORA, NHh*(NOPE+VDIM), (NHh*(NOPE+VDIM))/32, bx - 4608, tid);
    } else {
        do_transpose(wo, woh, NHh*VDIM, HID, HID/32, bx - 6656, tid);
    }
}

// ================= merged single-pass norm (q row + kv row per block) =======
__global__ void norm_fused(const float* __restrict__ qc, const float* __restrict__ qw,
                           const float* __restrict__ kvt, const float* __restrict__ kvw,
                           const int* __restrict__ pos,
                           __half* __restrict__ qch, __half* __restrict__ kvch,
                           __half* __restrict__ kfh) {
    GRID_SYNC();
    __shared__ float red2[8][2];
    __shared__ float rop[64];
    int tid = threadIdx.x, row = blockIdx.x;
    int lane = tid & 31, wrp = tid >> 5;

    // ---- loads (all issued up front) ----
    const float* r = qc + (size_t)row * QLORA;
    float4 v4 = *(const float4*)(r + 4 * tid);
    float2 v2 = *(const float2*)(r + 1024 + 2 * tid);
    const float* rk = kvt + (size_t)row * (KVLORA + ROPED);
    float2 k2 = *(const float2*)(rk + 2 * tid);

    if (tid < 32) {
        float p = (float)pos[row];
        float inv_freq = __expf(-(float)tid * (LN10K / 32.f));
        float c, s;
        __sincosf(p * inv_freq, &s, &c);
        float x1 = rk[KVLORA + tid];
        float x2 = rk[KVLORA + 32 + tid];
        rop[tid]      = x1 * c - x2 * s;
        rop[tid + 32] = x2 * c + x1 * s;
    }

    float ssq = v4.x*v4.x + v4.y*v4.y + v4.z*v4.z + v4.w*v4.w + v2.x*v2.x + v2.y*v2.y;
    float ssk = k2.x*k2.x + k2.y*k2.y;

    // ---- paired reduction ----
#pragma unroll
    for (int off = 16; off > 0; off >>= 1) {
        ssq += __shfl_xor_sync(0xffffffffu, ssq, off);
        ssk += __shfl_xor_sync(0xffffffffu, ssk, off);
    }
    if (lane == 0) { red2[wrp][0] = ssq; red2[wrp][1] = ssk; }
    __syncthreads();
    float a0 = (tid < 8) ? red2[tid][0] : 0.f;
    float a1 = (tid < 8) ? red2[tid][1] : 0.f;
#pragma unroll
    for (int off = 4; off > 0; off >>= 1) {
        a0 += __shfl_xor_sync(0xffffffffu, a0, off);
        a1 += __shfl_xor_sync(0xffffffffu, a1, off);
    }
    if (tid == 0) { red2[0][0] = a0; red2[0][1] = a1; }
    __syncthreads();
    float scq = rsqrtf(red2[0][0] / (float)QLORA + 1e-6f);
    float sck = rsqrtf(red2[0][1] / (float)KVLORA + 1e-6f);

    // ---- emit ----
    float4 w4 = *(const float4*)(qw + 4 * tid);
    float2 w2 = *(const float2*)(qw + 1024 + 2 * tid);
    __half* o = qch + (size_t)row * QLORA;
    *(__half2*)(o + 4*tid)        = __floats2half2_rn(v4.x*scq*w4.x, v4.y*scq*w4.y);
    *(__half2*)(o + 4*tid + 2)    = __floats2half2_rn(v4.z*scq*w4.z, v4.w*scq*w4.w);
    *(__half2*)(o + 1024 + 2*tid) = __floats2half2_rn(v2.x*scq*w2.x, v2.y*scq*w2.y);

    float2 kw2 = *(const float2*)(kvw + 2 * tid);
    *(__half2*)(kvch + (size_t)row * KVLORA + 2*tid) =
        __floats2half2_rn(k2.x*sck*kw2.x, k2.y*sck*kw2.y);

    int b = row >> 11, srow = row & 2047;
#pragma unroll
    for (int e = tid; e < NHh * ROPED; e += 256) {
        int h = e >> 6, d = e & 63;
        size_t oo = ((size_t)(b * NHh + h) * Ss + srow) * QKD + NOPE + d;
        kfh[oo] = __float2half(rop[d]);
    }
}

// ================= fp16 flash v5: q-tile 64, kv-tile 64, 128 thr, 2 CTA/SM ==
#define FQ_PITCH 400
#define FV_PITCH 272
#define FQ_SZ    (64*FQ_PITCH)            // 25600
#define FK_SZ    (64*FQ_PITCH)            // 25600
#define FV_SZ    (64*FV_PITCH)            // 17408
#define F_OFF_K  FQ_SZ
#define F_OFF_V  (F_OFF_K + 2*FK_SZ)      // 76800
#define FLASH_SMEM (F_OFF_V + 2*FV_SZ)    // 111616

__global__ void __launch_bounds__(128, 2) flash_mma(
    const __half* __restrict__ qh, const __half* __restrict__ kh,
    const __half* __restrict__ vh, __half* __restrict__ oh) {
    GRID_SYNC();
    extern __shared__ char sm[];
    uint32_t sb = smem_u32(sm);

    int qt = (gridDim.x - 1) - blockIdx.x;   // heavy CTAs first
    int h = blockIdx.y, b = blockIdx.z;
    int q0 = qt * 64;
    int tid = threadIdx.x, lane = tid & 31, w = tid >> 5;
    int bh = b * NHh + h;

    const __half* qhb = qh + ((size_t)bh * Ss + q0) * QKD;
    const __half* khb = kh + (size_t)bh * Ss * QKD;
    const __half* vhb = vh + (size_t)bh * Ss * VDIM;

    // ---- load Q tile (group 0): 64 rows x 24 chunks = 1536 over 128 thr ----
#pragma unroll
    for (int i = 0; i < 12; i++) {
        int e = tid + i * 128;
        int r = e / 24, c = e % 24;
        CP_ASYNC16(sb + r * FQ_PITCH + c * 16, qhb + (size_t)r * QKD + c * 8);
    }
    CP_COMMIT();

    auto load_kv = [&](int kt, int s) {
        int k0 = kt * 64;
        uint32_t kst = sb + F_OFF_K + s * FK_SZ;
        uint32_t vst = sb + F_OFF_V + s * FV_SZ;
#pragma unroll
        for (int i = 0; i < 12; i++) {
            int e = tid + i * 128;           // 1536 chunks
            int r = e / 24, c = e % 24;
            CP_ASYNC16(kst + r * FQ_PITCH + c * 16, khb + (size_t)(k0 + r) * QKD + c * 8);
        }
#pragma unroll
        for (int i = 0; i < 8; i++) {
            int e = tid + i * 128;           // 1024 chunks
            int r = e >> 4, c = e & 15;
            CP_ASYNC16(vst + r * FV_PITCH + c * 16, vhb + (size_t)(k0 + r) * VDIM + c * 8);
        }
        CP_COMMIT();
    };

    load_kv(0, 0);                           // group 1

    int a_r = w * 16 + (lane & 15);
    int a_c8 = (lane >> 4) << 3;
    int b_r = ((lane >> 4) << 3) + (lane & 7);
    int b_c8 = ((lane >> 3) & 1) << 3;
    int vt_r = lane & 15;
    int vt_c8 = (lane >> 4) << 3;

    int g = lane >> 2, t4 = lane & 3;

    // ---- wait for Q, hoist Q fragments into registers ----
    CP_WAIT1();
    __syncthreads();
    uint32_t qfr[12][4];
#pragma unroll
    for (int kk = 0; kk < 12; kk++)
        LDSM4(qfr[kk], sb + (uint32_t)(a_r * FQ_PITCH + (kk * 16 + a_c8) * 2));

    float m0 = -INFINITY, m1 = -INFINITY, l0 = 0.f, l1 = 0.f;
    float O[16][4];
#pragma unroll
    for (int j = 0; j < 16; j++)
#pragma unroll
        for (int k = 0; k < 4; k++) O[j][k] = 0.f;

    int qrow0 = q0 + w * 16 + g;
    int qrow1 = qrow0 + 8;

    int nkt = qt + 1;                        // kv tiles of 64 up to diagonal

    for (int kt = 0; kt < nkt; kt++) {
        int s = kt & 1;
        if (kt + 1 < nkt) { load_kv(kt + 1, s ^ 1); CP_WAIT1(); }
        else              { CP_WAIT0(); }
        __syncthreads();

        uint32_t kst = sb + F_OFF_K + s * FK_SZ;
        uint32_t vst = sb + F_OFF_V + s * FV_SZ;
        int k0 = kt * 64;

        float sc[8][4];
#pragma unroll
        for (int j = 0; j < 8; j++)
#pragma unroll
            for (int k = 0; k < 4; k++) sc[j][k] = 0.f;

#pragma unroll
        for (int kk = 0; kk < 12; kk++) {
#pragma unroll
            for (int nb = 0; nb < 4; nb++) {
                uint32_t bhf[4];
                LDSM4(bhf, kst + (uint32_t)((nb * 16 + b_r) * FQ_PITCH + (kk * 16 + b_c8) * 2));
                MMA16816(sc[2*nb],   qfr[kk], bhf[0], bhf[1]);
                MMA16816(sc[2*nb+1], qfr[kk], bhf[2], bhf[3]);
            }
        }

        // causal mask: only the diagonal tile can cross
        if (kt == qt) {
#pragma unroll
            for (int j = 0; j < 8; j++) {
                int col = k0 + j * 8 + t4 * 2;
                if (col     > qrow0) sc[j][0] = -INFINITY;
                if (col + 1 > qrow0) sc[j][1] = -INFINITY;
                if (col     > qrow1) sc[j][2] = -INFINITY;
                if (col + 1 > qrow1) sc[j][3] = -INFINITY;
            }
        }

        float rm0 = -INFINITY, rm1 = -INFINITY;
#pragma unroll
        for (int j = 0; j < 8; j++) {
            rm0 = fmaxf(rm0, fmaxf(sc[j][0], sc[j][1]));
            rm1 = fmaxf(rm1, fmaxf(sc[j][2], sc[j][3]));
        }
        rm0 = fmaxf(rm0, __shfl_xor_sync(0xffffffffu, rm0, 1));
        rm0 = fmaxf(rm0, __shfl_xor_sync(0xffffffffu, rm0, 2));
        rm1 = fmaxf(rm1, __shfl_xor_sync(0xffffffffu, rm1, 1));
        rm1 = fmaxf(rm1, __shfl_xor_sync(0xffffffffu, rm1, 2));
        float nm0 = fmaxf(m0, rm0), nm1 = fmaxf(m1, rm1);
        float rs0 = 0.f, rs1 = 0.f;
#pragma unroll
        for (int j = 0; j < 8; j++) {
            sc[j][0] = __expf(sc[j][0] - nm0);
            sc[j][1] = __expf(sc[j][1] - nm0);
            sc[j][2] = __expf(sc[j][2] - nm1);
            sc[j][3] = __expf(sc[j][3] - nm1);
            rs0 += sc[j][0] + sc[j][1];
            rs1 += sc[j][2] + sc[j][3];
        }
        rs0 += __shfl_xor_sync(0xffffffffu, rs0, 1);
        rs0 += __shfl_xor_sync(0xffffffffu, rs0, 2);
        rs1 += __shfl_xor_sync(0xffffffffu, rs1, 1);
        rs1 += __shfl_xor_sync(0xffffffffu, rs1, 2);
        float al0 = __expf(m0 - nm0), al1 = __expf(m1 - nm1);
        l0 = l0 * al0 + rs0; l1 = l1 * al1 + rs1;
        m0 = nm0; m1 = nm1;
#pragma unroll
        for (int j = 0; j < 16; j++) {
            O[j][0] *= al0; O[j][1] *= al0;
            O[j][2] *= al1; O[j][3] *= al1;
        }

        uint32_t ph2[8][2];
#pragma unroll
        for (int j = 0; j < 8; j++) {
            __half2 p01 = __floats2half2_rn(sc[j][0], sc[j][1]);
            __half2 p23 = __floats2half2_rn(sc[j][2], sc[j][3]);
            ph2[j][0] = *(uint32_t*)&p01;
            ph2[j][1] = *(uint32_t*)&p23;
        }

#pragma unroll
        for (int kk = 0; kk < 4; kk++) {
            uint32_t ah[4] = { ph2[2*kk][0], ph2[2*kk][1], ph2[2*kk+1][0], ph2[2*kk+1][1] };
#pragma unroll
            for (int j2 = 0; j2 < 8; j2++) {
                uint32_t vhf[4];
                LDSM4T(vhf, vst + (uint32_t)((kk * 16 + vt_r) * FV_PITCH + (j2 * 16 + vt_c8) * 2));
                MMA16816(O[2*j2],   ah, vhf[0], vhf[1]);
                MMA16816(O[2*j2+1], ah, vhf[2], vhf[3]);
            }
        }
        __syncthreads();
    }

    float inv0 = 1.f / l0, inv1 = 1.f / l1;
    size_t ob0 = ((size_t)(b * Ss + qrow0)) * (NHh * VDIM) + h * VDIM;
    size_t ob1 = ((size_t)(b * Ss + qrow1)) * (NHh * VDIM) + h * VDIM;
#pragma unroll
    for (int j = 0; j < 16; j++) {
        int d = j * 8 + t4 * 2;
        *(__half2*)(oh + ob0 + d) = __floats2half2_rn(O[j][0] * inv0, O[j][1] * inv0);
        *(__half2*)(oh + ob1 + d) = __floats2half2_rn(O[j][2] * inv1, O[j][3] * inv1);
    }
}

// ================= launch =================
extern "C" void kernel_launch(void* const* d_in, const int* in_sizes, int n_in,
                              void* d_out, int out_size) {
    const float* hs     = (const float*)d_in[0];
    const int*   pos    = (const int*)  d_in[1];
    const float* w_q_a  = (const float*)d_in[3];
    const float* q_ln   = (const float*)d_in[4];
    const float* w_q_b  = (const float*)d_in[5];
    const float* w_kv_a = (const float*)d_in[6];
    const float* kv_ln  = (const float*)d_in[7];
    const float* w_kv_b = (const float*)d_in[8];
    const float* w_o    = (const float*)d_in[9];
    float* out = (float*)d_out;

    float *qc, *kvt;
    cudaGetSymbolAddress((void**)&qc,  g_qc);
    cudaGetSymbolAddress((void**)&kvt, g_kvt);

    __half *hs_h,*qc_h,*kvc_h,*at_h;
    __half *wqa_h,*wqb_h,*wkva_h,*wkvb_h,*wo_h;
    __half *qfh,*kfh,*vfh;
    cudaGetSymbolAddress((void**)&hs_h,  g_hs_h);
    cudaGetSymbolAddress((void**)&qc_h,  g_qc_h);
    cudaGetSymbolAddress((void**)&kvc_h, g_kvc_h);
    cudaGetSymbolAddress((void**)&at_h,  g_at_h);
    cudaGetSymbolAddress((void**)&wqa_h, g_wqa_h);
    cudaGetSymbolAddress((void**)&wqb_h, g_wqb_h);
    cudaGetSymbolAddress((void**)&wkva_h,g_wkva_h);
    cudaGetSymbolAddress((void**)&wkvb_h,g_wkvb_h);
    cudaGetSymbolAddress((void**)&wo_h,  g_wo_h);
    cudaGetSymbolAddress((void**)&qfh,   g_qfh);
    cudaGetSymbolAddress((void**)&kfh,   g_kfh);
    cudaGetSymbolAddress((void**)&vfh,   g_vfh);

    cudaFuncSetAttribute(gemm_a, cudaFuncAttributeMaxDynamicSharedMemorySize, GEMM_SMEM);
    cudaFuncSetAttribute(gemm_b, cudaFuncAttributeMaxDynamicSharedMemorySize, GEMM_SMEM);
    cudaFuncSetAttribute(gemm_c, cudaFuncAttributeMaxDynamicSharedMemorySize, GEMM_SMEM);
    cudaFuncSetAttribute(flash_mma, cudaFuncAttributeMaxDynamicSharedMemorySize, FLASH_SMEM);

    cudaStream_t s2;
    cudaStreamCreateWithFlags(&s2, cudaStreamNonBlocking);
    cudaEvent_t evFork, evJoin;
    cudaEventCreateWithFlags(&evFork, cudaEventDisableTiming);
    cudaEventCreateWithFlags(&evJoin, cudaEventDisableTiming);

    cudaEventRecord(evFork, 0);
    cudaStreamWaitEvent(s2, evFork, 0);
    prep_aux<<<4608 + 2048 + 4096, 256, 0, s2>>>(w_q_b, wqb_h, w_kv_b, wkvb_h, w_o, wo_h);
    cudaEventRecord(evJoin, s2);

    prep_main<<<4096 + 3072 + 1280, 256>>>(hs, hs_h, w_q_a, wqa_h, w_kv_a, wkva_h);

    cudaLaunchAttribute pdlAttr[1];
    pdlAttr[0].id = cudaLaunchAttributeProgrammaticStreamSerialization;
    pdlAttr[0].val.programmaticStreamSerializationAllowed = 1;

    {
        cudaLaunchConfig_t cfg{};
        cfg.gridDim = dim3(12 + WKVA_NPAD/128, ROWS/128);
        cfg.blockDim = dim3(256);
        cfg.dynamicSmemBytes = GEMM_SMEM;
        cfg.stream = 0; cfg.attrs = pdlAttr; cfg.numAttrs = 1;
        cudaLaunchKernelEx(&cfg, gemm_a, hs_h, wqa_h, wkva_h, qc, kvt);
    }
    {
        cudaLaunchConfig_t cfg{};
        cfg.gridDim = dim3(ROWS);
        cfg.blockDim = dim3(256);
        cfg.dynamicSmemBytes = 0;
        cfg.stream = 0; cfg.attrs = pdlAttr; cfg.numAttrs = 1;
        cudaLaunchKernelEx(&cfg, norm_fused, (const float*)qc, q_ln, (const float*)kvt, kv_ln,
                           pos, qc_h, kvc_h, kfh);
    }

    cudaStreamWaitEvent(0, evJoin, 0);

    {
        cudaLaunchConfig_t cfg{};
        cfg.gridDim = dim3(24 + 32, ROWS/128);
        cfg.blockDim = dim3(256);
        cfg.dynamicSmemBytes = GEMM_SMEM;
        cfg.stream = 0; cfg.attrs = pdlAttr; cfg.numAttrs = 1;
        cudaLaunchKernelEx(&cfg, gemm_b, (const __half*)qc_h, (const __half*)wqb_h,
                           (const __half*)kvc_h, (const __half*)wkvb_h, pos, qfh, kfh, vfh);
    }
    {
        cudaLaunchConfig_t cfg{};
        cfg.gridDim = dim3(Ss/64, NHh, Bb);
        cfg.blockDim = dim3(128);
        cfg.dynamicSmemBytes = FLASH_SMEM;
        cfg.stream = 0; cfg.attrs = pdlAttr; cfg.numAttrs = 1;
        cudaLaunchKernelEx(&cfg, flash_mma, (const __half*)qfh, (const __half*)kfh,
                           (const __half*)vfh, at_h);
    }
    {
        cudaLaunchConfig_t cfg{};
        cfg.gridDim = dim3(HID/128, ROWS/128);
        cfg.blockDim = dim3(256);
        cfg.dynamicSmemBytes = GEMM_SMEM;
        cfg.stream = 0; cfg.attrs = pdlAttr; cfg.numAttrs = 1;
        cudaLaunchKernelEx(&cfg, gemm_c, (const __half*)at_h, (const __half*)wo_h, out);
    }

    cudaEventDestroy(evFork);
    cudaEventDestroy(evJoin);
    cudaStreamDestroy(s2);
}

// round 17
// speedup vs baseline: 1.0406x; 1.0174x over previous
#include <cuda_runtime.h>
#include <cuda_fp16.h>
#include <math.h>
#include <cstdint>

// ---------------- problem constants ----------------
#define Bb   2
#define Ss   2048
#define HID  2048
#define NHh  16
#define QLORA 1536
#define KVLORA 512
#define NOPE 128
#define ROPED 64
#define VDIM 128
#define QKD  192
#define ROWS (Bb*Ss)          // 4096
#define WKVA_NPAD 640
#define SCALEF 0.07216878364870322f
#define LN10K  9.210340371976184f

// ---------------- fp32 scratch ----------------
__device__ float g_qc   [(size_t)ROWS * QLORA];
__device__ float g_kvt  [(size_t)ROWS * (KVLORA+ROPED)];

// ---------------- fp16 activations ----------------
__device__ __half g_hs_h [(size_t)ROWS*HID];
__device__ __half g_qc_h [(size_t)ROWS*QLORA];
__device__ __half g_kvc_h[(size_t)ROWS*KVLORA];
__device__ __half g_at_h [(size_t)ROWS*NHh*VDIM];

// ---------------- fp16 transposed weights [N,K] ----------------
__device__ __half g_wqa_h [(size_t)QLORA*HID];
__device__ __half g_wqb_h [(size_t)(NHh*QKD)*QLORA];
__device__ __half g_wkva_h[(size_t)WKVA_NPAD*HID];
__device__ __half g_wkvb_h[(size_t)(NHh*(NOPE+VDIM))*KVLORA];
__device__ __half g_wo_h  [(size_t)HID*(NHh*VDIM)];

// ---------------- flash fp16 buffers, [b,h,s,d] ----------------
__device__ __half g_qfh[(size_t)ROWS*NHh*QKD];
__device__ __half g_kfh[(size_t)ROWS*NHh*QKD];
__device__ __half g_vfh[(size_t)ROWS*NHh*VDIM];

// ================= helpers =================
__device__ __forceinline__ uint32_t smem_u32(const void* p) {
    uint32_t a;
    asm("{ .reg .u64 t; cvta.to.shared.u64 t, %1; cvt.u32.u64 %0, t; }" : "=r"(a) : "l"(p));
    return a;
}

#define LDSM4(r, a) asm volatile( \
    "ldmatrix.sync.aligned.m8n8.x4.shared.b16 {%0,%1,%2,%3}, [%4];" \
    : "=r"((r)[0]),"=r"((r)[1]),"=r"((r)[2]),"=r"((r)[3]) : "r"(a))

#define LDSM4T(r, a) asm volatile( \
    "ldmatrix.sync.aligned.m8n8.x4.trans.shared.b16 {%0,%1,%2,%3}, [%4];" \
    : "=r"((r)[0]),"=r"((r)[1]),"=r"((r)[2]),"=r"((r)[3]) : "r"(a))

#define MMA16816(d, a, b0v, b1v) asm volatile( \
    "mma.sync.aligned.m16n8k16.row.col.f32.f16.f16.f32 " \
    "{%0,%1,%2,%3},{%4,%5,%6,%7},{%8,%9},{%0,%1,%2,%3};" \
    : "+f"((d)[0]),"+f"((d)[1]),"+f"((d)[2]),"+f"((d)[3]) \
    : "r"((a)[0]),"r"((a)[1]),"r"((a)[2]),"r"((a)[3]), "r"(b0v),"r"(b1v))

#define CP_ASYNC16(sa, ga) asm volatile( \
    "cp.async.cg.shared.global [%0], [%1], 16;" :: "r"(sa), "l"(ga))
#define CP_COMMIT() asm volatile("cp.async.commit_group;" ::: "memory")
#define CP_WAIT1()  asm volatile("cp.async.wait_group 1;" ::: "memory")
#define CP_WAIT0()  asm volatile("cp.async.wait_group 0;" ::: "memory")

#define GRID_SYNC() cudaGridDependencySynchronize()

// ================= fp16 HMMA GEMM mainloop, BK=64, warp tile 64x64 =========
// CTA tile 128x128, 128 threads (warp grid 2x2). 2 CTAs/SM.
#define BK 64
#define PITCHH 72
#define TILE_B (128*PITCHH*2)          // 18432
#define STAGE_B (2*TILE_B)             // 36864
#define NSTAGE 3
#define GEMM_SMEM (NSTAGE*STAGE_B)     // 110592

__device__ __forceinline__ void gemm_mainloop(
    const __half* __restrict__ gA, const __half* __restrict__ gB, int K,
    uint32_t sbase, float acc[4][8][4],
    int tid, int lane, int warpM, int warpN) {

    auto issue_loads = [&](int c, int s) {
        int k0 = c * BK;
        uint32_t st = sbase + s * STAGE_B;
#pragma unroll
        for (int j = 0; j < 8; j++) {
            int seg = tid + j * 128;           // 1024 chunks per operand
            int r = seg >> 3, cc = seg & 7;
            CP_ASYNC16(st + r * (PITCHH * 2) + cc * 16, gA + (size_t)r * K + k0 + cc * 8);
            CP_ASYNC16(st + TILE_B + r * (PITCHH * 2) + cc * 16, gB + (size_t)r * K + k0 + cc * 8);
        }
        CP_COMMIT();
    };

#pragma unroll
    for (int i = 0; i < 4; i++)
#pragma unroll
        for (int j = 0; j < 8; j++)
#pragma unroll
            for (int k = 0; k < 4; k++) acc[i][j][k] = 0.f;

    int a_r = warpM * 64 + (lane & 15);
    int a_c8 = (lane >> 4) << 3;
    int b_r = warpN * 64 + ((lane >> 4) << 3) + (lane & 7);
    int b_c8 = ((lane >> 3) & 1) << 3;

    auto compute = [&](int s) {
        uint32_t st = sbase + s * STAGE_B;
#pragma unroll
        for (int ki = 0; ki < 4; ki++) {
            uint32_t ah[4][4];
#pragma unroll
            for (int mi = 0; mi < 4; mi++) {
                uint32_t off = (uint32_t)((a_r + mi * 16) * (PITCHH * 2) + (ki * 16 + a_c8) * 2);
                LDSM4(ah[mi], st + off);
            }
            uint32_t bh[4][4];
#pragma unroll
            for (int nb = 0; nb < 4; nb++) {
                uint32_t off = (uint32_t)((b_r + nb * 16) * (PITCHH * 2) + (ki * 16 + b_c8) * 2);
                LDSM4(bh[nb], st + TILE_B + off);
            }
#pragma unroll
            for (int mi = 0; mi < 4; mi++)
#pragma unroll
                for (int nb = 0; nb < 4; nb++) {
                    MMA16816(acc[mi][2*nb],   ah[mi], bh[nb][0], bh[nb][1]);
                    MMA16816(acc[mi][2*nb+1], ah[mi], bh[nb][2], bh[nb][3]);
                }
        }
    };

    int nc = K / BK;
    issue_loads(0, 0);
    issue_loads(1, 1);
    for (int c = 0; c < nc; c++) {
        int s = c % NSTAGE;
        if (c + 1 < nc) { CP_WAIT1(); } else { CP_WAIT0(); }
        __syncthreads();
        if (c + 2 < nc) issue_loads(c + 2, (c + 2) % NSTAGE);
        compute(s);
    }
}

// ================= merged G1+G3 =================
__global__ void __launch_bounds__(128, 2) gemm_a(
    const __half* __restrict__ hs, const __half* __restrict__ wqa,
    const __half* __restrict__ wkva,
    float* __restrict__ qc, float* __restrict__ kvt) {
    GRID_SYNC();
    extern __shared__ char sm[];
    uint32_t sbase = smem_u32(sm);
    int tid = threadIdx.x, lane = tid & 31, wid = tid >> 5;
    int warpM = wid & 1, warpN = wid >> 1;
    int row0 = blockIdx.y * 128;
    int bx = blockIdx.x;

    const __half* B;
    float* C; int cN, col0, Nlim;
    if (bx < 12) { col0 = bx * 128;        B = wqa  + (size_t)col0 * HID; C = qc;  cN = QLORA; Nlim = QLORA; }
    else         { col0 = (bx - 12) * 128; B = wkva + (size_t)col0 * HID; C = kvt; cN = KVLORA+ROPED; Nlim = KVLORA+ROPED; }

    float acc[4][8][4];
    gemm_mainloop(hs + (size_t)row0 * HID, B, HID, sbase, acc, tid, lane, warpM, warpN);

    int g = lane >> 2, t = lane & 3;
#pragma unroll
    for (int mi = 0; mi < 4; mi++)
#pragma unroll
        for (int n8 = 0; n8 < 8; n8++) {
            int col = col0 + warpN * 64 + n8 * 8 + t * 2;
            if (col < Nlim) {
                int r0 = row0 + warpM * 64 + mi * 16 + g;
                float* p0 = C + (size_t)r0 * cN + col;
                p0[0] = acc[mi][n8][0]; p0[1] = acc[mi][n8][1];
                float* p1 = p0 + (size_t)8 * cN;
                p1[0] = acc[mi][n8][2]; p1[1] = acc[mi][n8][3];
            }
        }
}

// ================= merged G2+G4 =================
__global__ void __launch_bounds__(128, 2) gemm_b(
    const __half* __restrict__ qch, const __half* __restrict__ wqb,
    const __half* __restrict__ kvch, const __half* __restrict__ wkvb,
    const int* __restrict__ pos,
    __half* __restrict__ qfh, __half* __restrict__ kfh, __half* __restrict__ vfh) {
    GRID_SYNC();
    extern __shared__ char sm[];
    uint32_t sbase = smem_u32(sm);
    int tid = threadIdx.x, lane = tid & 31, wid = tid >> 5;
    int warpM = wid & 1, warpN = wid >> 1;
    int row0 = blockIdx.y * 128;
    int bx = blockIdx.x;
    int g = lane >> 2, t4 = lane & 3;

    if (bx < 24) {
        int col0 = bx * 128;
        float acc[4][8][4];
        gemm_mainloop(qch + (size_t)row0 * QLORA, wqb + (size_t)col0 * QLORA, QLORA,
                      sbase, acc, tid, lane, warpM, warpN);

        int colw = col0 + warpN * 64;
        int hH = colw / 192;
        int dbase = colw % 192;
        if (dbase != 128) {
#pragma unroll
            for (int mi = 0; mi < 4; mi++)
#pragma unroll
                for (int rr = 0; rr < 2; rr++) {
                    int row = row0 + warpM * 64 + mi * 16 + g + rr * 8;
                    int b = row >> 11, srow = row & 2047;
                    size_t obase = ((size_t)(b * NHh + hH) * Ss + srow) * QKD;
#pragma unroll
                    for (int n8 = 0; n8 < 8; n8++) {
                        int d = dbase + n8 * 8 + t4 * 2;
                        *(__half2*)(qfh + obase + d) = __floats2half2_rn(
                            acc[mi][n8][rr*2] * SCALEF, acc[mi][n8][rr*2+1] * SCALEF);
                    }
                }
        } else {
#pragma unroll
            for (int mi = 0; mi < 4; mi++)
#pragma unroll
                for (int rr = 0; rr < 2; rr++) {
                    int row = row0 + warpM * 64 + mi * 16 + g + rr * 8;
                    int b = row >> 11, srow = row & 2047;
                    float p = (float)pos[b * Ss + srow];
                    size_t obase = ((size_t)(b * NHh + hH) * Ss + srow) * QKD;
#pragma unroll
                    for (int n8 = 0; n8 < 4; n8++) {
                        int j0 = n8 * 8 + t4 * 2;
                        float if0 = __expf(-(float)j0 * (LN10K / 32.f));
                        float if1 = __expf(-(float)(j0 + 1) * (LN10K / 32.f));
                        float s0, c0, s1, c1;
                        __sincosf(p * if0, &s0, &c0);
                        __sincosf(p * if1, &s1, &c1);
                        float x1a = acc[mi][n8][rr*2],   x2a = acc[mi][n8+4][rr*2];
                        float x1b = acc[mi][n8][rr*2+1], x2b = acc[mi][n8+4][rr*2+1];
                        *(__half2*)(qfh + obase + 128 + j0) = __floats2half2_rn(
                            (x1a * c0 - x2a * s0) * SCALEF, (x1b * c1 - x2b * s1) * SCALEF);
                        *(__half2*)(qfh + obase + 160 + j0) = __floats2half2_rn(
                            (x2a * c0 + x1a * s0) * SCALEF, (x2b * c1 + x1b * s1) * SCALEF);
                    }
                }
        }
    } else {
        int col0 = (bx - 24) * 128;
        float acc[4][8][4];
        gemm_mainloop(kvch + (size_t)row0 * KVLORA, wkvb + (size_t)col0 * KVLORA, KVLORA,
                      sbase, acc, tid, lane, warpM, warpN);

        int hH = col0 >> 8;
        int isV = (col0 >> 7) & 1;
        __half* D = isV ? vfh : kfh;
        int stride = isV ? VDIM : QKD;
#pragma unroll
        for (int mi = 0; mi < 4; mi++)
#pragma unroll
            for (int n8 = 0; n8 < 8; n8++) {
                int col = col0 + warpN * 64 + n8 * 8 + t4 * 2;
                int d = col & 127;
#pragma unroll
                for (int rr = 0; rr < 2; rr++) {
                    int r0 = row0 + warpM * 64 + mi * 16 + g + rr * 8;
                    int b = r0 >> 11, srow = r0 & 2047;
                    size_t o = ((size_t)(b * NHh + hH) * Ss + srow) * stride + d;
                    *(__half2*)(D + o) = __floats2half2_rn(acc[mi][n8][rr*2], acc[mi][n8][rr*2+1]);
                }
            }
    }
}

// ================= G5 =================
__global__ void __launch_bounds__(128, 2) gemm_c(
    const __half* __restrict__ at, const __half* __restrict__ wo,
    float* __restrict__ out) {
    GRID_SYNC();
    extern __shared__ char sm[];
    uint32_t sbase = smem_u32(sm);
    int tid = threadIdx.x, lane = tid & 31, wid = tid >> 5;
    int warpM = wid & 1, warpN = wid >> 1;
    int row0 = blockIdx.y * 128, col0 = blockIdx.x * 128;

    float acc[4][8][4];
    gemm_mainloop(at + (size_t)row0 * HID, wo + (size_t)col0 * HID, HID,
                  sbase, acc, tid, lane, warpM, warpN);

    int g = lane >> 2, t = lane & 3;
#pragma unroll
    for (int mi = 0; mi < 4; mi++)
#pragma unroll
        for (int n8 = 0; n8 < 8; n8++) {
            int col = col0 + warpN * 64 + n8 * 8 + t * 2;
            int r0 = row0 + warpM * 64 + mi * 16 + g;
            float* p0 = out + (size_t)r0 * HID + col;
            p0[0] = acc[mi][n8][0]; p0[1] = acc[mi][n8][1];
            float* p1 = p0 + (size_t)8 * HID;
            p1[0] = acc[mi][n8][2]; p1[1] = acc[mi][n8][3];
        }
}

// ================= merged prep kernels =================
__device__ __forceinline__ void do_transpose(
    const float* __restrict__ W, __half* __restrict__ Th,
    int K, int srcN, int colTiles, int tile, int tid) {
    __shared__ float t[32][33];
    int n0 = (tile % colTiles) * 32, k0 = (tile / colTiles) * 32;
    int tx = tid & 31, ty = tid >> 5;
#pragma unroll
    for (int i = 0; i < 4; i++) {
        int k = k0 + ty + i * 8, n = n0 + tx;
        t[ty + i * 8][tx] = (n < srcN) ? W[(size_t)k * srcN + n] : 0.f;
    }
    __syncthreads();
#pragma unroll
    for (int i = 0; i < 4; i++) {
        int n = n0 + ty + i * 8;
        Th[(size_t)n * K + k0 + tx] = __float2half(t[tx][ty + i * 8]);
    }
}

__global__ void prep_main(const float* __restrict__ hs, __half* __restrict__ hsh,
                          const float* __restrict__ wqa, __half* __restrict__ wqah,
                          const float* __restrict__ wkva, __half* __restrict__ wkvah) {
    int bx = blockIdx.x, tid = threadIdx.x;
    if (bx < 4096) {
        size_t i = ((size_t)bx * 256 + tid) * 8;
        float4 v0 = *(const float4*)(hs + i);
        float4 v1 = *(const float4*)(hs + i + 4);
        *(__half2*)(hsh + i)     = __floats2half2_rn(v0.x, v0.y);
        *(__half2*)(hsh + i + 2) = __floats2half2_rn(v0.z, v0.w);
        *(__half2*)(hsh + i + 4) = __floats2half2_rn(v1.x, v1.y);
        *(__half2*)(hsh + i + 6) = __floats2half2_rn(v1.z, v1.w);
    } else if (bx < 4096 + 3072) {
        do_transpose(wqa, wqah, HID, QLORA, QLORA/32, bx - 4096, tid);
    } else {
        do_transpose(wkva, wkvah, HID, KVLORA+ROPED, WKVA_NPAD/32, bx - 7168, tid);
    }
}

__global__ void prep_aux(const float* __restrict__ wqb, __half* __restrict__ wqbh,
                         const float* __restrict__ wkvb, __half* __restrict__ wkvbh,
                         const float* __restrict__ wo, __half* __restrict__ woh) {
    int bx = blockIdx.x, tid = threadIdx.x;
    if (bx < 4608) {
        do_transpose(wqb, wqbh, QLORA, NHh*QKD, (NHh*QKD)/32, bx, tid);
    } else if (bx < 4608 + 2048) {
        do_transpose(wkvb, wkvbh, KVLORA, NHh*(NOPE+VDIM), (NHh*(NOPE+VDIM))/32, bx - 4608, tid);
    } else {
        do_transpose(wo, woh, NHh*VDIM, HID, HID/32, bx - 6656, tid);
    }
}

// ================= merged single-pass norm (q row + kv row per block) =======
__global__ void norm_fused(const float* __restrict__ qc, const float* __restrict__ qw,
                           const float* __restrict__ kvt, const float* __restrict__ kvw,
                           const int* __restrict__ pos,
                           __half* __restrict__ qch, __half* __restrict__ kvch,
                           __half* __restrict__ kfh) {
    GRID_SYNC();
    __shared__ float red2[8][2];
    __shared__ float rop[64];
    int tid = threadIdx.x, row = blockIdx.x;
    int lane = tid & 31, wrp = tid >> 5;

    const float* r = qc + (size_t)row * QLORA;
    float4 v4 = *(const float4*)(r + 4 * tid);
    float2 v2 = *(const float2*)(r + 1024 + 2 * tid);
    const float* rk = kvt + (size_t)row * (KVLORA + ROPED);
    float2 k2 = *(const float2*)(rk + 2 * tid);

    if (tid < 32) {
        float p = (float)pos[row];
        float inv_freq = __expf(-(float)tid * (LN10K / 32.f));
        float c, s;
        __sincosf(p * inv_freq, &s, &c);
        float x1 = rk[KVLORA + tid];
        float x2 = rk[KVLORA + 32 + tid];
        rop[tid]      = x1 * c - x2 * s;
        rop[tid + 32] = x2 * c + x1 * s;
    }

    float ssq = v4.x*v4.x + v4.y*v4.y + v4.z*v4.z + v4.w*v4.w + v2.x*v2.x + v2.y*v2.y;
    float ssk = k2.x*k2.x + k2.y*k2.y;

#pragma unroll
    for (int off = 16; off > 0; off >>= 1) {
        ssq += __shfl_xor_sync(0xffffffffu, ssq, off);
        ssk += __shfl_xor_sync(0xffffffffu, ssk, off);
    }
    if (lane == 0) { red2[wrp][0] = ssq; red2[wrp][1] = ssk; }
    __syncthreads();
    float a0 = (tid < 8) ? red2[tid][0] : 0.f;
    float a1 = (tid < 8) ? red2[tid][1] : 0.f;
#pragma unroll
    for (int off = 4; off > 0; off >>= 1) {
        a0 += __shfl_xor_sync(0xffffffffu, a0, off);
        a1 += __shfl_xor_sync(0xffffffffu, a1, off);
    }
    if (tid == 0) { red2[0][0] = a0; red2[0][1] = a1; }
    __syncthreads();
    float scq = rsqrtf(red2[0][0] / (float)QLORA + 1e-6f);
    float sck = rsqrtf(red2[0][1] / (float)KVLORA + 1e-6f);

    float4 w4 = *(const float4*)(qw + 4 * tid);
    float2 w2 = *(const float2*)(qw + 1024 + 2 * tid);
    __half* o = qch + (size_t)row * QLORA;
    *(__half2*)(o + 4*tid)        = __floats2half2_rn(v4.x*scq*w4.x, v4.y*scq*w4.y);
    *(__half2*)(o + 4*tid + 2)    = __floats2half2_rn(v4.z*scq*w4.z, v4.w*scq*w4.w);
    *(__half2*)(o + 1024 + 2*tid) = __floats2half2_rn(v2.x*scq*w2.x, v2.y*scq*w2.y);

    float2 kw2 = *(const float2*)(kvw + 2 * tid);
    *(__half2*)(kvch + (size_t)row * KVLORA + 2*tid) =
        __floats2half2_rn(k2.x*sck*kw2.x, k2.y*sck*kw2.y);

    int b = row >> 11, srow = row & 2047;
#pragma unroll
    for (int e = tid; e < NHh * ROPED; e += 256) {
        int h = e >> 6, d = e & 63;
        size_t oo = ((size_t)(b * NHh + h) * Ss + srow) * QKD + NOPE + d;
        kfh[oo] = __float2half(rop[d]);
    }
}

// ================= fp16 flash v5 (R16): q 64, kv 64, 128 thr, 2 CTA/SM ======
#define FQ_PITCH 400
#define FV_PITCH 272
#define FQ_SZ    (64*FQ_PITCH)            // 25600
#define FK_SZ    (64*FQ_PITCH)            // 25600
#define FV_SZ    (64*FV_PITCH)            // 17408
#define F_OFF_K  FQ_SZ
#define F_OFF_V  (F_OFF_K + 2*FK_SZ)      // 76800
#define FLASH_SMEM (F_OFF_V + 2*FV_SZ)    // 111616

__global__ void __launch_bounds__(128, 2) flash_mma(
    const __half* __restrict__ qh, const __half* __restrict__ kh,
    const __half* __restrict__ vh, __half* __restrict__ oh) {
    GRID_SYNC();
    extern __shared__ char sm[];
    uint32_t sb = smem_u32(sm);

    int qt = (gridDim.x - 1) - blockIdx.x;
    int h = blockIdx.y, b = blockIdx.z;
    int q0 = qt * 64;
    int tid = threadIdx.x, lane = tid & 31, w = tid >> 5;
    int bh = b * NHh + h;

    const __half* qhb = qh + ((size_t)bh * Ss + q0) * QKD;
    const __half* khb = kh + (size_t)bh * Ss * QKD;
    const __half* vhb = vh + (size_t)bh * Ss * VDIM;

#pragma unroll
    for (int i = 0; i < 12; i++) {
        int e = tid + i * 128;
        int r = e / 24, c = e % 24;
        CP_ASYNC16(sb + r * FQ_PITCH + c * 16, qhb + (size_t)r * QKD + c * 8);
    }
    CP_COMMIT();

    auto load_kv = [&](int kt, int s) {
        int k0 = kt * 64;
        uint32_t kst = sb + F_OFF_K + s * FK_SZ;
        uint32_t vst = sb + F_OFF_V + s * FV_SZ;
#pragma unroll
        for (int i = 0; i < 12; i++) {
            int e = tid + i * 128;
            int r = e / 24, c = e % 24;
            CP_ASYNC16(kst + r * FQ_PITCH + c * 16, khb + (size_t)(k0 + r) * QKD + c * 8);
        }
#pragma unroll
        for (int i = 0; i < 8; i++) {
            int e = tid + i * 128;
            int r = e >> 4, c = e & 15;
            CP_ASYNC16(vst + r * FV_PITCH + c * 16, vhb + (size_t)(k0 + r) * VDIM + c * 8);
        }
        CP_COMMIT();
    };

    load_kv(0, 0);

    int a_r = w * 16 + (lane & 15);
    int a_c8 = (lane >> 4) << 3;
    int b_r = ((lane >> 4) << 3) + (lane & 7);
    int b_c8 = ((lane >> 3) & 1) << 3;
    int vt_r = lane & 15;
    int vt_c8 = (lane >> 4) << 3;

    int g = lane >> 2, t4 = lane & 3;

    CP_WAIT1();
    __syncthreads();
    uint32_t qfr[12][4];
#pragma unroll
    for (int kk = 0; kk < 12; kk++)
        LDSM4(qfr[kk], sb + (uint32_t)(a_r * FQ_PITCH + (kk * 16 + a_c8) * 2));

    float m0 = -INFINITY, m1 = -INFINITY, l0 = 0.f, l1 = 0.f;
    float O[16][4];
#pragma unroll
    for (int j = 0; j < 16; j++)
#pragma unroll
        for (int k = 0; k < 4; k++) O[j][k] = 0.f;

    int qrow0 = q0 + w * 16 + g;
    int qrow1 = qrow0 + 8;

    int nkt = qt + 1;

    for (int kt = 0; kt < nkt; kt++) {
        int s = kt & 1;
        if (kt + 1 < nkt) { load_kv(kt + 1, s ^ 1); CP_WAIT1(); }
        else              { CP_WAIT0(); }
        __syncthreads();

        uint32_t kst = sb + F_OFF_K + s * FK_SZ;
        uint32_t vst = sb + F_OFF_V + s * FV_SZ;
        int k0 = kt * 64;

        float sc[8][4];
#pragma unroll
        for (int j = 0; j < 8; j++)
#pragma unroll
            for (int k = 0; k < 4; k++) sc[j][k] = 0.f;

#pragma unroll
        for (int kk = 0; kk < 12; kk++) {
#pragma unroll
            for (int nb = 0; nb < 4; nb++) {
                uint32_t bhf[4];
                LDSM4(bhf, kst + (uint32_t)((nb * 16 + b_r) * FQ_PITCH + (kk * 16 + b_c8) * 2));
                MMA16816(sc[2*nb],   qfr[kk], bhf[0], bhf[1]);
                MMA16816(sc[2*nb+1], qfr[kk], bhf[2], bhf[3]);
            }
        }

        if (kt == qt) {
#pragma unroll
            for (int j = 0; j < 8; j++) {
                int col = k0 + j * 8 + t4 * 2;
                if (col     > qrow0) sc[j][0] = -INFINITY;
                if (col + 1 > qrow0) sc[j][1] = -INFINITY;
                if (col     > qrow1) sc[j][2] = -INFINITY;
                if (col + 1 > qrow1) sc[j][3] = -INFINITY;
            }
        }

        float rm0 = -INFINITY, rm1 = -INFINITY;
#pragma unroll
        for (int j = 0; j < 8; j++) {
            rm0 = fmaxf(rm0, fmaxf(sc[j][0], sc[j][1]));
            rm1 = fmaxf(rm1, fmaxf(sc[j][2], sc[j][3]));
        }
        rm0 = fmaxf(rm0, __shfl_xor_sync(0xffffffffu, rm0, 1));
        rm0 = fmaxf(rm0, __shfl_xor_sync(0xffffffffu, rm0, 2));
        rm1 = fmaxf(rm1, __shfl_xor_sync(0xffffffffu, rm1, 1));
        rm1 = fmaxf(rm1, __shfl_xor_sync(0xffffffffu, rm1, 2));
        float nm0 = fmaxf(m0, rm0), nm1 = fmaxf(m1, rm1);
        float rs0 = 0.f, rs1 = 0.f;
#pragma unroll
        for (int j = 0; j < 8; j++) {
            sc[j][0] = __expf(sc[j][0] - nm0);
            sc[j][1] = __expf(sc[j][1] - nm0);
            sc[j][2] = __expf(sc[j][2] - nm1);
            sc[j][3] = __expf(sc[j][3] - nm1);
            rs0 += sc[j][0] + sc[j][1];
            rs1 += sc[j][2] + sc[j][3];
        }
        rs0 += __shfl_xor_sync(0xffffffffu, rs0, 1);
        rs0 += __shfl_xor_sync(0xffffffffu, rs0, 2);
        rs1 += __shfl_xor_sync(0xffffffffu, rs1, 1);
        rs1 += __shfl_xor_sync(0xffffffffu, rs1, 2);
        float al0 = __expf(m0 - nm0), al1 = __expf(m1 - nm1);
        l0 = l0 * al0 + rs0; l1 = l1 * al1 + rs1;
        m0 = nm0; m1 = nm1;
#pragma unroll
        for (int j = 0; j < 16; j++) {
            O[j][0] *= al0; O[j][1] *= al0;
            O[j][2] *= al1; O[j][3] *= al1;
        }

        uint32_t ph2[8][2];
#pragma unroll
        for (int j = 0; j < 8; j++) {
            __half2 p01 = __floats2half2_rn(sc[j][0], sc[j][1]);
            __half2 p23 = __floats2half2_rn(sc[j][2], sc[j][3]);
            ph2[j][0] = *(uint32_t*)&p01;
            ph2[j][1] = *(uint32_t*)&p23;
        }

#pragma unroll
        for (int kk = 0; kk < 4; kk++) {
            uint32_t ah[4] = { ph2[2*kk][0], ph2[2*kk][1], ph2[2*kk+1][0], ph2[2*kk+1][1] };
#pragma unroll
            for (int j2 = 0; j2 < 8; j2++) {
                uint32_t vhf[4];
                LDSM4T(vhf, vst + (uint32_t)((kk * 16 + vt_r) * FV_PITCH + (j2 * 16 + vt_c8) * 2));
                MMA16816(O[2*j2],   ah, vhf[0], vhf[1]);
                MMA16816(O[2*j2+1], ah, vhf[2], vhf[3]);
            }
        }
        __syncthreads();
    }

    float inv0 = 1.f / l0, inv1 = 1.f / l1;
    size_t ob0 = ((size_t)(b * Ss + qrow0)) * (NHh * VDIM) + h * VDIM;
    size_t ob1 = ((size_t)(b * Ss + qrow1)) * (NHh * VDIM) + h * VDIM;
#pragma unroll
    for (int j = 0; j < 16; j++) {
        int d = j * 8 + t4 * 2;
        *(__half2*)(oh + ob0 + d) = __floats2half2_rn(O[j][0] * inv0, O[j][1] * inv0);
        *(__half2*)(oh + ob1 + d) = __floats2half2_rn(O[j][2] * inv1, O[j][3] * inv1);
    }
}

// ================= launch =================
extern "C" void kernel_launch(void* const* d_in, const int* in_sizes, int n_in,
                              void* d_out, int out_size) {
    const float* hs     = (const float*)d_in[0];
    const int*   pos    = (const int*)  d_in[1];
    const float* w_q_a  = (const float*)d_in[3];
    const float* q_ln   = (const float*)d_in[4];
    const float* w_q_b  = (const float*)d_in[5];
    const float* w_kv_a = (const float*)d_in[6];
    const float* kv_ln  = (const float*)d_in[7];
    const float* w_kv_b = (const float*)d_in[8];
    const float* w_o    = (const float*)d_in[9];
    float* out = (float*)d_out;

    float *qc, *kvt;
    cudaGetSymbolAddress((void**)&qc,  g_qc);
    cudaGetSymbolAddress((void**)&kvt, g_kvt);

    __half *hs_h,*qc_h,*kvc_h,*at_h;
    __half *wqa_h,*wqb_h,*wkva_h,*wkvb_h,*wo_h;
    __half *qfh,*kfh,*vfh;
    cudaGetSymbolAddress((void**)&hs_h,  g_hs_h);
    cudaGetSymbolAddress((void**)&qc_h,  g_qc_h);
    cudaGetSymbolAddress((void**)&kvc_h, g_kvc_h);
    cudaGetSymbolAddress((void**)&at_h,  g_at_h);
    cudaGetSymbolAddress((void**)&wqa_h, g_wqa_h);
    cudaGetSymbolAddress((void**)&wqb_h, g_wqb_h);
    cudaGetSymbolAddress((void**)&wkva_h,g_wkva_h);
    cudaGetSymbolAddress((void**)&wkvb_h,g_wkvb_h);
    cudaGetSymbolAddress((void**)&wo_h,  g_wo_h);
    cudaGetSymbolAddress((void**)&qfh,   g_qfh);
    cudaGetSymbolAddress((void**)&kfh,   g_kfh);
    cudaGetSymbolAddress((void**)&vfh,   g_vfh);

    cudaFuncSetAttribute(gemm_a, cudaFuncAttributeMaxDynamicSharedMemorySize, GEMM_SMEM);
    cudaFuncSetAttribute(gemm_b, cudaFuncAttributeMaxDynamicSharedMemorySize, GEMM_SMEM);
    cudaFuncSetAttribute(gemm_c, cudaFuncAttributeMaxDynamicSharedMemorySize, GEMM_SMEM);
    cudaFuncSetAttribute(flash_mma, cudaFuncAttributeMaxDynamicSharedMemorySize, FLASH_SMEM);

    cudaStream_t s2;
    cudaStreamCreateWithFlags(&s2, cudaStreamNonBlocking);
    cudaEvent_t evFork, evJoin;
    cudaEventCreateWithFlags(&evFork, cudaEventDisableTiming);
    cudaEventCreateWithFlags(&evJoin, cudaEventDisableTiming);

    cudaEventRecord(evFork, 0);
    cudaStreamWaitEvent(s2, evFork, 0);
    prep_aux<<<4608 + 2048 + 4096, 256, 0, s2>>>(w_q_b, wqb_h, w_kv_b, wkvb_h, w_o, wo_h);
    cudaEventRecord(evJoin, s2);

    prep_main<<<4096 + 3072 + 1280, 256>>>(hs, hs_h, w_q_a, wqa_h, w_kv_a, wkva_h);

    cudaLaunchAttribute pdlAttr[1];
    pdlAttr[0].id = cudaLaunchAttributeProgrammaticStreamSerialization;
    pdlAttr[0].val.programmaticStreamSerializationAllowed = 1;

    {
        cudaLaunchConfig_t cfg{};
        cfg.gridDim = dim3(12 + WKVA_NPAD/128, ROWS/128);
        cfg.blockDim = dim3(128);
        cfg.dynamicSmemBytes = GEMM_SMEM;
        cfg.stream = 0; cfg.attrs = pdlAttr; cfg.numAttrs = 1;
        cudaLaunchKernelEx(&cfg, gemm_a, hs_h, wqa_h, wkva_h, qc, kvt);
    }
    {
        cudaLaunchConfig_t cfg{};
        cfg.gridDim = dim3(ROWS);
        cfg.blockDim = dim3(256);
        cfg.dynamicSmemBytes = 0;
        cfg.stream = 0; cfg.attrs = pdlAttr; cfg.numAttrs = 1;
        cudaLaunchKernelEx(&cfg, norm_fused, (const float*)qc, q_ln, (const float*)kvt, kv_ln,
                           pos, qc_h, kvc_h, kfh);
    }

    cudaStreamWaitEvent(0, evJoin, 0);

    {
        cudaLaunchConfig_t cfg{};
        cfg.gridDim = dim3(24 + 32, ROWS/128);
        cfg.blockDim = dim3(128);
        cfg.dynamicSmemBytes = GEMM_SMEM;
        cfg.stream = 0; cfg.attrs = pdlAttr; cfg.numAttrs = 1;
        cudaLaunchKernelEx(&cfg, gemm_b, (const __half*)qc_h, (const __half*)wqb_h,
                           (const __half*)kvc_h, (const __half*)wkvb_h, pos, qfh, kfh, vfh);
    }
    {
        cudaLaunchConfig_t cfg{};
        cfg.gridDim = dim3(Ss/64, NHh, Bb);
        cfg.blockDim = dim3(128);
        cfg.dynamicSmemBytes = FLASH_SMEM;
        cfg.stream = 0; cfg.attrs = pdlAttr; cfg.numAttrs = 1;
        cudaLaunchKernelEx(&cfg, flash_mma, (const __half*)qfh, (const __half*)kfh,
                           (const __half*)vfh, at_h);
    }
    {
        cudaLaunchConfig_t cfg{};
        cfg.gridDim = dim3(HID/128, ROWS/128);
        cfg.blockDim = dim3(128);
        cfg.dynamicSmemBytes = GEMM_SMEM;
        cfg.stream = 0; cfg.attrs = pdlAttr; cfg.numAttrs = 1;
        cudaLaunchKernelEx(&cfg, gemm_c, (const __half*)at_h, (const __half*)wo_h, out);
    }

    cudaEventDestroy(evFork);
    cudaEventDestroy(evJoin);
    cudaStreamDestroy(s2);
}